// round 1
// baseline (speedup 1.0000x reference)
#include <cuda_runtime.h>
#include <math.h>

#define Hc   224
#define Wc   224
#define HWc  (Hc * Wc)       // 50176
#define Bc   2
#define MTOK (Bc * HWc)      // 100352
#define Ec   64
#define NHc  4
#define DHc  16
#define DFFc 2048

// ---------------- scratch (static device globals; no allocs) ----------------
__device__ float g_col [MTOK * 576];     // im2col scratch (max K = 64*9)
__device__ float g_bufA[MTOK * 64];      // e1 / attn-proj out / ffn out
__device__ float g_t   [MTOK * 64];      // enc2 output == tokens
__device__ float g_qkv [MTOK * 192];
__device__ float g_attn[MTOK * 64];
__device__ float g_t1  [MTOK * 64];      // after LN1
__device__ float g_t2  [MTOK * 64];      // after LN2 (enc2 for sf path)
__device__ float g_hid [MTOK * DFFc];    // FFN hidden
__device__ float g_sf1 [MTOK * 32];
__device__ float g_filt[MTOK * 9];
__device__ float g_fus [MTOK];
__device__ float g_d1  [MTOK * 64];

// ---------------- im2col: 3x3, pad 1, stride 1 ----------------
// dst[m*K + ci*9 + ky*3+kx], K = Cin*9; m = b*HW + y*W + x
__global__ void im2col_k(const float* __restrict__ src, float* __restrict__ dst,
                         int Cin, int nchw) {
    long tid = (long)blockIdx.x * blockDim.x + threadIdx.x;
    long total = (long)MTOK * Cin * 9;
    if (tid >= total) return;
    int kk = (int)(tid % 9);
    long t2 = tid / 9;
    int ci = (int)(t2 % Cin);
    int m  = (int)(t2 / Cin);
    int b = m / HWc, pix = m % HWc;
    int y = pix / Wc, x = pix % Wc;
    int ky = kk / 3, kx = kk % 3;
    int py = y + ky - 1, px = x + kx - 1;
    float v = 0.f;
    if (py >= 0 && py < Hc && px >= 0 && px < Wc) {
        if (nchw) v = src[((size_t)(b * Cin + ci) * HWc) + py * Wc + px];
        else      v = src[((size_t)(b * HWc + py * Wc + px)) * Cin + ci];
    }
    dst[(size_t)m * (Cin * 9) + ci * 9 + kk] = v;
}

// ---------------- GEMM: C[M,N] = act(A[M,K] * W[N,K]^T + bias[N]) ----------------
// act: 0=none 1=relu 2=sigmoid
#define BM 64
#define BN 64
#define BK 16
__global__ void gemm_k(const float* __restrict__ A, const float* __restrict__ W,
                       const float* __restrict__ bias, float* __restrict__ C,
                       int M, int N, int K, int act) {
    __shared__ float As[BK][BM];
    __shared__ float Ws[BK][BN];
    int tid = threadIdx.x;            // 256 threads
    int tx = tid % 16;                // N dir
    int ty = tid / 16;                // M dir
    int m0 = blockIdx.y * BM;
    int n0 = blockIdx.x * BN;

    float acc[4][4];
#pragma unroll
    for (int i = 0; i < 4; i++)
#pragma unroll
        for (int j = 0; j < 4; j++) acc[i][j] = 0.f;

    for (int k0 = 0; k0 < K; k0 += BK) {
        // load A tile (BM x BK) and W tile (BN x BK)
#pragma unroll
        for (int i = tid; i < BM * BK; i += 256) {
            int r = i / BK, c = i % BK;
            int gm = m0 + r, gk = k0 + c;
            As[c][r] = (gm < M && gk < K) ? A[(size_t)gm * K + gk] : 0.f;
        }
#pragma unroll
        for (int i = tid; i < BN * BK; i += 256) {
            int r = i / BK, c = i % BK;
            int gn = n0 + r, gk = k0 + c;
            Ws[c][r] = (gn < N && gk < K) ? W[(size_t)gn * K + gk] : 0.f;
        }
        __syncthreads();
#pragma unroll
        for (int kk = 0; kk < BK; kk++) {
            float4 a = *(const float4*)&As[kk][ty * 4];
            float4 w = *(const float4*)&Ws[kk][tx * 4];
            float av[4] = {a.x, a.y, a.z, a.w};
            float wv[4] = {w.x, w.y, w.z, w.w};
#pragma unroll
            for (int i = 0; i < 4; i++)
#pragma unroll
                for (int j = 0; j < 4; j++) acc[i][j] += av[i] * wv[j];
        }
        __syncthreads();
    }

#pragma unroll
    for (int i = 0; i < 4; i++) {
        int gm = m0 + ty * 4 + i;
        if (gm >= M) continue;
#pragma unroll
        for (int j = 0; j < 4; j++) {
            int gn = n0 + tx * 4 + j;
            if (gn >= N) continue;
            float v = acc[i][j] + bias[gn];
            if (act == 1) v = fmaxf(v, 0.f);
            else if (act == 2) v = 1.f / (1.f + expf(-v));
            C[(size_t)gm * N + gn] = v;
        }
    }
}

// ---------------- attention: per (pixel n, head h), S=2 across batch ----------------
__global__ void attn_k(const float* __restrict__ qkv, float* __restrict__ out) {
    int idx = blockIdx.x * blockDim.x + threadIdx.x;
    if (idx >= HWc * NHc) return;
    int n = idx / NHc, h = idx % NHc;
    const float* r0 = qkv + (size_t)n * 192 + h * DHc;            // s = 0
    const float* r1 = qkv + (size_t)(HWc + n) * 192 + h * DHc;    // s = 1
    const float *q0 = r0, *k0 = r0 + 64, *v0 = r0 + 128;
    const float *q1 = r1, *k1 = r1 + 64, *v1 = r1 + 128;
    float s00 = 0, s01 = 0, s10 = 0, s11 = 0;
#pragma unroll
    for (int d = 0; d < DHc; d++) {
        float a = q0[d], b = q1[d], c = k0[d], e = k1[d];
        s00 += a * c; s01 += a * e; s10 += b * c; s11 += b * e;
    }
    const float sc = 0.25f;  // 1/sqrt(16)
    s00 *= sc; s01 *= sc; s10 *= sc; s11 *= sc;
    // softmax row 0
    float m0 = fmaxf(s00, s01);
    float e00 = expf(s00 - m0), e01 = expf(s01 - m0);
    float p00 = e00 / (e00 + e01), p01 = e01 / (e00 + e01);
    // softmax row 1
    float m1 = fmaxf(s10, s11);
    float e10 = expf(s10 - m1), e11 = expf(s11 - m1);
    float p10 = e10 / (e10 + e11), p11 = e11 / (e10 + e11);
    float* o0 = out + (size_t)n * 64 + h * DHc;
    float* o1 = out + (size_t)(HWc + n) * 64 + h * DHc;
#pragma unroll
    for (int d = 0; d < DHc; d++) {
        o0[d] = p00 * v0[d] + p01 * v1[d];
        o1[d] = p10 * v0[d] + p11 * v1[d];
    }
}

// ---------------- residual + LayerNorm over E=64 (warp per token) ----------------
__global__ void ln_res_k(const float* __restrict__ a, const float* __restrict__ b,
                         const float* __restrict__ g, const float* __restrict__ be,
                         float* __restrict__ out) {
    int gt = blockIdx.x * blockDim.x + threadIdx.x;
    int warp = gt / 32, lane = gt % 32;
    if (warp >= MTOK) return;
    size_t base = (size_t)warp * 64;
    float x0 = a[base + lane] + b[base + lane];
    float x1 = a[base + 32 + lane] + b[base + 32 + lane];
    float s = x0 + x1;
#pragma unroll
    for (int o = 16; o > 0; o >>= 1) s += __shfl_xor_sync(0xffffffffu, s, o);
    float mu = s * (1.f / 64.f);
    float c0 = x0 - mu, c1 = x1 - mu;
    float sq = c0 * c0 + c1 * c1;
#pragma unroll
    for (int o = 16; o > 0; o >>= 1) sq += __shfl_xor_sync(0xffffffffu, sq, o);
    float r = rsqrtf(sq * (1.f / 64.f) + 1e-5f);
    out[base + lane]      = g[lane] * c0 * r + be[lane];
    out[base + 32 + lane] = g[lane + 32] * c1 * r + be[lane + 32];
}

// ---------------- per-pixel 3x3 adaptive filter on s = sum_c x ----------------
__global__ void fuse_k(const float* __restrict__ xin, const float* __restrict__ filt,
                       float* __restrict__ out) {
    int m = blockIdx.x * blockDim.x + threadIdx.x;
    if (m >= MTOK) return;
    int b = m / HWc, pix = m % HWc;
    int y = pix / Wc, x = pix % Wc;
    const float* xb = xin + (size_t)b * 3 * HWc;
    float acc = 0.f;
#pragma unroll
    for (int u = 0; u < 3; u++) {
#pragma unroll
        for (int v = 0; v < 3; v++) {
            int py = y + u - 1, px = x + v - 1;
            if (py < 0 || py >= Hc || px < 0 || px >= Wc) continue;
            int p = py * Wc + px;
            float s = xb[p] + xb[HWc + p] + xb[2 * HWc + p];
            acc += filt[(size_t)m * 9 + u * 3 + v] * s;
        }
    }
    out[m] = acc;
}

// ---------------- host orchestration ----------------
static void run_gemm(const float* A, const float* W, const float* bias, float* C,
                     int M, int N, int K, int act) {
    dim3 grid((N + BN - 1) / BN, (M + BM - 1) / BM);
    gemm_k<<<grid, 256>>>(A, W, bias, C, M, N, K, act);
}

extern "C" void kernel_launch(void* const* d_in, const int* in_sizes, int n_in,
                              void* d_out, int out_size) {
    const float* x        = (const float*)d_in[0];
    const float* enc_w1   = (const float*)d_in[1];
    const float* enc_b1   = (const float*)d_in[2];
    const float* enc_w2   = (const float*)d_in[3];
    const float* enc_b2   = (const float*)d_in[4];
    const float* in_pw    = (const float*)d_in[5];
    const float* in_pb    = (const float*)d_in[6];
    const float* out_pw   = (const float*)d_in[7];
    const float* out_pb   = (const float*)d_in[8];
    const float* ln1_g    = (const float*)d_in[9];
    const float* ln1_b    = (const float*)d_in[10];
    const float* ffn_w1   = (const float*)d_in[11];
    const float* ffn_b1   = (const float*)d_in[12];
    const float* ffn_w2   = (const float*)d_in[13];
    const float* ffn_b2   = (const float*)d_in[14];
    const float* ln2_g    = (const float*)d_in[15];
    const float* ln2_b    = (const float*)d_in[16];
    const float* sf_w1    = (const float*)d_in[17];
    const float* sf_b1    = (const float*)d_in[18];
    const float* sf_w2    = (const float*)d_in[19];
    const float* sf_b2    = (const float*)d_in[20];
    const float* dec_w1   = (const float*)d_in[21];
    const float* dec_b1   = (const float*)d_in[22];
    const float* dec_w2   = (const float*)d_in[23];
    const float* dec_b2   = (const float*)d_in[24];
    float* out = (float*)d_out;

    float *col, *bufA, *t, *qkv, *attn, *t1, *t2, *hid, *sf1, *filt, *fus, *d1;
    cudaGetSymbolAddress((void**)&col,  g_col);
    cudaGetSymbolAddress((void**)&bufA, g_bufA);
    cudaGetSymbolAddress((void**)&t,    g_t);
    cudaGetSymbolAddress((void**)&qkv,  g_qkv);
    cudaGetSymbolAddress((void**)&attn, g_attn);
    cudaGetSymbolAddress((void**)&t1,   g_t1);
    cudaGetSymbolAddress((void**)&t2,   g_t2);
    cudaGetSymbolAddress((void**)&hid,  g_hid);
    cudaGetSymbolAddress((void**)&sf1,  g_sf1);
    cudaGetSymbolAddress((void**)&filt, g_filt);
    cudaGetSymbolAddress((void**)&fus,  g_fus);
    cudaGetSymbolAddress((void**)&d1,   g_d1);

    const int M = MTOK;
    auto blocks = [](long total, int thr) { return (int)((total + thr - 1) / thr); };

    // ---- encoder ----
    im2col_k<<<blocks((long)M * 3 * 9, 256), 256>>>(x, col, 3, 1);
    run_gemm(col, enc_w1, enc_b1, bufA, M, 64, 27, 1);            // e1 (relu), ch-last
    im2col_k<<<blocks((long)M * 64 * 9, 256), 256>>>(bufA, col, 64, 0);
    run_gemm(col, enc_w2, enc_b2, t, M, 64, 576, 1);              // e2 == tokens

    // ---- transformer ----
    run_gemm(t, in_pw, in_pb, qkv, M, 192, 64, 0);
    attn_k<<<blocks((long)HWc * NHc, 256), 256>>>(qkv, attn);
    run_gemm(attn, out_pw, out_pb, bufA, M, 64, 64, 0);           // attn projection
    ln_res_k<<<blocks((long)M * 32, 256), 256>>>(t, bufA, ln1_g, ln1_b, t1);
    run_gemm(t1, ffn_w1, ffn_b1, hid, M, DFFc, 64, 1);            // FFN up + relu
    run_gemm(hid, ffn_w2, ffn_b2, bufA, M, 64, DFFc, 0);          // FFN down
    ln_res_k<<<blocks((long)M * 32, 256), 256>>>(t1, bufA, ln2_g, ln2_b, t2);

    // ---- spatial filter branch ----
    im2col_k<<<blocks((long)M * 64 * 9, 256), 256>>>(t2, col, 64, 0);
    run_gemm(col, sf_w1, sf_b1, sf1, M, 32, 576, 0);              // no relu
    im2col_k<<<blocks((long)M * 32 * 9, 256), 256>>>(sf1, col, 32, 0);
    run_gemm(col, sf_w2, sf_b2, filt, M, 9, 288, 0);
    fuse_k<<<blocks((long)M, 256), 256>>>(x, filt, fus);

    // ---- decoder ----
    im2col_k<<<blocks((long)M * 1 * 9, 256), 256>>>(fus, col, 1, 0);
    run_gemm(col, dec_w1, dec_b1, d1, M, 64, 9, 1);
    im2col_k<<<blocks((long)M * 64 * 9, 256), 256>>>(d1, col, 64, 0);
    run_gemm(col, dec_w2, dec_b2, out, M, 1, 576, 2);             // sigmoid
}

// round 2
// speedup vs baseline: 1.6107x; 1.6107x over previous
#include <cuda_runtime.h>
#include <math.h>

#define Hc   224
#define Wc   224
#define HWc  (Hc * Wc)       // 50176
#define Bc   2
#define MTOK (Bc * HWc)      // 100352
#define Ec   64
#define NHc  4
#define DHc  16
#define DFFc 2048

// ---------------- scratch (static device globals; no allocs) ----------------
__device__ float g_col [MTOK * 576];     // im2col scratch (max K = 64*9)
__device__ float g_bufA[MTOK * 64];      // e1 / attn-proj out / ffn out
__device__ float g_t   [MTOK * 64];      // enc2 output == tokens
__device__ float g_qkv [MTOK * 192];
__device__ float g_attn[MTOK * 64];
__device__ float g_t1  [MTOK * 64];      // after LN1
__device__ float g_t2  [MTOK * 64];      // after LN2 (enc2 for sf path)
__device__ float g_hid [MTOK * DFFc];    // FFN hidden
__device__ float g_sf1 [MTOK * 32];
__device__ float g_filt[MTOK * 9];
__device__ float g_fus [MTOK];
__device__ float g_d1  [MTOK * 64];

// ---------------- im2col: 3x3, pad 1, stride 1 ----------------
__global__ void im2col_k(const float* __restrict__ src, float* __restrict__ dst,
                         int Cin, int nchw) {
    long tid = (long)blockIdx.x * blockDim.x + threadIdx.x;
    long total = (long)MTOK * Cin * 9;
    if (tid >= total) return;
    int kk = (int)(tid % 9);
    long t2 = tid / 9;
    int ci = (int)(t2 % Cin);
    int m  = (int)(t2 / Cin);
    int b = m / HWc, pix = m % HWc;
    int y = pix / Wc, x = pix % Wc;
    int ky = kk / 3, kx = kk % 3;
    int py = y + ky - 1, px = x + kx - 1;
    float v = 0.f;
    if (py >= 0 && py < Hc && px >= 0 && px < Wc) {
        if (nchw) v = src[((size_t)(b * Cin + ci) * HWc) + py * Wc + px];
        else      v = src[((size_t)(b * HWc + py * Wc + px)) * Cin + ci];
    }
    dst[(size_t)m * (Cin * 9) + ci * 9 + kk] = v;
}

// ---------------- tiled GEMM: C[M,N] = act(A[M,K] * W[N,K]^T + bias[N]) --------
// act: 0=none 1=relu 2=sigmoid. M must be a multiple of BM (100352 = 128*784 = 256*392).
template<int BM, int BN, int BK, int TM, int TN>
__global__ void __launch_bounds__(256, 1)
gemm_t(const float* __restrict__ A, const float* __restrict__ W,
       const float* __restrict__ bias, float* __restrict__ C,
       int M, int N, int K, int act) {
    constexpr int SA = BM + 8;    // stride mod 32 == 8 -> conflict-free STS/LDS
    constexpr int SW = BN + 8;
    constexpr int TX = BN / TN;
    constexpr int TY = BM / TM;
    static_assert(TX * TY == 256, "256 threads required");
    __shared__ float As[BK][SA];
    __shared__ float Ws[BK][SW];

    const int tid = threadIdx.x;
    const int tx = tid % TX;
    const int ty = tid / TX;
    const size_t m0 = (size_t)blockIdx.y * BM;
    const int n0 = blockIdx.x * BN;

    float acc[TM][TN];
#pragma unroll
    for (int i = 0; i < TM; i++)
#pragma unroll
        for (int j = 0; j < TN; j++) acc[i][j] = 0.f;

    const bool k_vec = ((K & 3) == 0);

    for (int k0 = 0; k0 < K; k0 += BK) {
        if (k_vec && (k0 + BK <= K)) {
            // vector loads, conflict-free transposed stores
#pragma unroll
            for (int i = tid; i < BM * BK / 4; i += 256) {
                int r = i / (BK / 4);
                int c4 = i % (BK / 4);
                float4 v = *(const float4*)&A[(m0 + r) * K + k0 + c4 * 4];
                As[c4 * 4 + 0][r] = v.x;
                As[c4 * 4 + 1][r] = v.y;
                As[c4 * 4 + 2][r] = v.z;
                As[c4 * 4 + 3][r] = v.w;
            }
#pragma unroll
            for (int i = tid; i < BN * BK / 4; i += 256) {
                int r = i / (BK / 4);
                int c4 = i % (BK / 4);
                int gn = n0 + r;
                float4 v = make_float4(0.f, 0.f, 0.f, 0.f);
                if (gn < N) v = *(const float4*)&W[(size_t)gn * K + k0 + c4 * 4];
                Ws[c4 * 4 + 0][r] = v.x;
                Ws[c4 * 4 + 1][r] = v.y;
                Ws[c4 * 4 + 2][r] = v.z;
                Ws[c4 * 4 + 3][r] = v.w;
            }
        } else {
            // scalar guarded path (K not multiple of 4 or tail tile)
            for (int i = tid; i < BM * BK; i += 256) {
                int r = i / BK, c = i % BK;
                int gk = k0 + c;
                As[c][r] = (gk < K) ? A[(m0 + r) * K + gk] : 0.f;
            }
            for (int i = tid; i < BN * BK; i += 256) {
                int r = i / BK, c = i % BK;
                int gn = n0 + r, gk = k0 + c;
                Ws[c][r] = (gn < N && gk < K) ? W[(size_t)gn * K + gk] : 0.f;
            }
        }
        __syncthreads();

#pragma unroll
        for (int kk = 0; kk < BK; kk++) {
            float a[TM], w[TN];
#pragma unroll
            for (int i = 0; i < TM; i += 4) {
                float4 v = *(const float4*)&As[kk][ty * TM + i];
                a[i] = v.x; a[i + 1] = v.y; a[i + 2] = v.z; a[i + 3] = v.w;
            }
            if constexpr (TN >= 4) {
#pragma unroll
                for (int j = 0; j < TN; j += 4) {
                    float4 v = *(const float4*)&Ws[kk][tx * TN + j];
                    w[j] = v.x; w[j + 1] = v.y; w[j + 2] = v.z; w[j + 3] = v.w;
                }
            } else if constexpr (TN == 2) {
                float2 v = *(const float2*)&Ws[kk][tx * 2];
                w[0] = v.x; w[1] = v.y;
            } else {
                w[0] = Ws[kk][tx];
            }
#pragma unroll
            for (int i = 0; i < TM; i++)
#pragma unroll
                for (int j = 0; j < TN; j++) acc[i][j] = fmaf(a[i], w[j], acc[i][j]);
        }
        __syncthreads();
    }

#pragma unroll
    for (int i = 0; i < TM; i++) {
        size_t gm = m0 + ty * TM + i;
#pragma unroll
        for (int j = 0; j < TN; j++) {
            int gn = n0 + tx * TN + j;
            if (gn >= N) continue;
            float v = acc[i][j] + bias[gn];
            if (act == 1) v = fmaxf(v, 0.f);
            else if (act == 2) v = 1.f / (1.f + expf(-v));
            C[gm * N + gn] = v;
        }
    }
}

// ---------------- attention: per (pixel n, head h), S=2 across batch ----------------
__global__ void attn_k(const float* __restrict__ qkv, float* __restrict__ out) {
    int idx = blockIdx.x * blockDim.x + threadIdx.x;
    if (idx >= HWc * NHc) return;
    int n = idx / NHc, h = idx % NHc;
    const float* r0 = qkv + (size_t)n * 192 + h * DHc;
    const float* r1 = qkv + (size_t)(HWc + n) * 192 + h * DHc;
    const float *q0 = r0, *k0 = r0 + 64, *v0 = r0 + 128;
    const float *q1 = r1, *k1 = r1 + 64, *v1 = r1 + 128;
    float s00 = 0, s01 = 0, s10 = 0, s11 = 0;
#pragma unroll
    for (int d = 0; d < DHc; d++) {
        float a = q0[d], b = q1[d], c = k0[d], e = k1[d];
        s00 += a * c; s01 += a * e; s10 += b * c; s11 += b * e;
    }
    const float sc = 0.25f;
    s00 *= sc; s01 *= sc; s10 *= sc; s11 *= sc;
    float m0 = fmaxf(s00, s01);
    float e00 = expf(s00 - m0), e01 = expf(s01 - m0);
    float p00 = e00 / (e00 + e01), p01 = e01 / (e00 + e01);
    float m1 = fmaxf(s10, s11);
    float e10 = expf(s10 - m1), e11 = expf(s11 - m1);
    float p10 = e10 / (e10 + e11), p11 = e11 / (e10 + e11);
    float* o0 = out + (size_t)n * 64 + h * DHc;
    float* o1 = out + (size_t)(HWc + n) * 64 + h * DHc;
#pragma unroll
    for (int d = 0; d < DHc; d++) {
        o0[d] = p00 * v0[d] + p01 * v1[d];
        o1[d] = p10 * v0[d] + p11 * v1[d];
    }
}

// ---------------- residual + LayerNorm over E=64 (warp per token) ----------------
__global__ void ln_res_k(const float* __restrict__ a, const float* __restrict__ b,
                         const float* __restrict__ g, const float* __restrict__ be,
                         float* __restrict__ out) {
    int gt = blockIdx.x * blockDim.x + threadIdx.x;
    int warp = gt / 32, lane = gt % 32;
    if (warp >= MTOK) return;
    size_t base = (size_t)warp * 64;
    float x0 = a[base + lane] + b[base + lane];
    float x1 = a[base + 32 + lane] + b[base + 32 + lane];
    float s = x0 + x1;
#pragma unroll
    for (int o = 16; o > 0; o >>= 1) s += __shfl_xor_sync(0xffffffffu, s, o);
    float mu = s * (1.f / 64.f);
    float c0 = x0 - mu, c1 = x1 - mu;
    float sq = c0 * c0 + c1 * c1;
#pragma unroll
    for (int o = 16; o > 0; o >>= 1) sq += __shfl_xor_sync(0xffffffffu, sq, o);
    float r = rsqrtf(sq * (1.f / 64.f) + 1e-5f);
    out[base + lane]      = g[lane] * c0 * r + be[lane];
    out[base + 32 + lane] = g[lane + 32] * c1 * r + be[lane + 32];
}

// ---------------- per-pixel 3x3 adaptive filter on s = sum_c x ----------------
__global__ void fuse_k(const float* __restrict__ xin, const float* __restrict__ filt,
                       float* __restrict__ out) {
    int m = blockIdx.x * blockDim.x + threadIdx.x;
    if (m >= MTOK) return;
    int b = m / HWc, pix = m % HWc;
    int y = pix / Wc, x = pix % Wc;
    const float* xb = xin + (size_t)b * 3 * HWc;
    float acc = 0.f;
#pragma unroll
    for (int u = 0; u < 3; u++) {
#pragma unroll
        for (int v = 0; v < 3; v++) {
            int py = y + u - 1, px = x + v - 1;
            if (py < 0 || py >= Hc || px < 0 || px >= Wc) continue;
            int p = py * Wc + px;
            float s = xb[p] + xb[HWc + p] + xb[2 * HWc + p];
            acc += filt[(size_t)m * 9 + u * 3 + v] * s;
        }
    }
    out[m] = acc;
}

// ---------------- host orchestration ----------------
// configs: A = 128x128 (8x8), B = 128x64 (8x4), B2 = 256x64 (16x4),
//          C = 128x32 (8x2), D = 128x16 (8x1)
static void gemm_cfgA(const float* A, const float* W, const float* b, float* C,
                      int M, int N, int K, int act) {
    dim3 g((N + 127) / 128, M / 128);
    gemm_t<128, 128, 16, 8, 8><<<g, 256>>>(A, W, b, C, M, N, K, act);
}
static void gemm_cfgB(const float* A, const float* W, const float* b, float* C,
                      int M, int N, int K, int act) {
    dim3 g((N + 63) / 64, M / 128);
    gemm_t<128, 64, 16, 8, 4><<<g, 256>>>(A, W, b, C, M, N, K, act);
}
static void gemm_cfgB2(const float* A, const float* W, const float* b, float* C,
                       int M, int N, int K, int act) {
    dim3 g((N + 63) / 64, M / 256);
    gemm_t<256, 64, 16, 16, 4><<<g, 256>>>(A, W, b, C, M, N, K, act);
}
static void gemm_cfgC(const float* A, const float* W, const float* b, float* C,
                      int M, int N, int K, int act) {
    dim3 g((N + 31) / 32, M / 128);
    gemm_t<128, 32, 16, 8, 2><<<g, 256>>>(A, W, b, C, M, N, K, act);
}
static void gemm_cfgD(const float* A, const float* W, const float* b, float* C,
                      int M, int N, int K, int act) {
    dim3 g((N + 15) / 16, M / 128);
    gemm_t<128, 16, 16, 8, 1><<<g, 256>>>(A, W, b, C, M, N, K, act);
}

extern "C" void kernel_launch(void* const* d_in, const int* in_sizes, int n_in,
                              void* d_out, int out_size) {
    const float* x        = (const float*)d_in[0];
    const float* enc_w1   = (const float*)d_in[1];
    const float* enc_b1   = (const float*)d_in[2];
    const float* enc_w2   = (const float*)d_in[3];
    const float* enc_b2   = (const float*)d_in[4];
    const float* in_pw    = (const float*)d_in[5];
    const float* in_pb    = (const float*)d_in[6];
    const float* out_pw   = (const float*)d_in[7];
    const float* out_pb   = (const float*)d_in[8];
    const float* ln1_g    = (const float*)d_in[9];
    const float* ln1_b    = (const float*)d_in[10];
    const float* ffn_w1   = (const float*)d_in[11];
    const float* ffn_b1   = (const float*)d_in[12];
    const float* ffn_w2   = (const float*)d_in[13];
    const float* ffn_b2   = (const float*)d_in[14];
    const float* ln2_g    = (const float*)d_in[15];
    const float* ln2_b    = (const float*)d_in[16];
    const float* sf_w1    = (const float*)d_in[17];
    const float* sf_b1    = (const float*)d_in[18];
    const float* sf_w2    = (const float*)d_in[19];
    const float* sf_b2    = (const float*)d_in[20];
    const float* dec_w1   = (const float*)d_in[21];
    const float* dec_b1   = (const float*)d_in[22];
    const float* dec_w2   = (const float*)d_in[23];
    const float* dec_b2   = (const float*)d_in[24];
    float* out = (float*)d_out;

    float *col, *bufA, *t, *qkv, *attn, *t1, *t2, *hid, *sf1, *filt, *fus, *d1;
    cudaGetSymbolAddress((void**)&col,  g_col);
    cudaGetSymbolAddress((void**)&bufA, g_bufA);
    cudaGetSymbolAddress((void**)&t,    g_t);
    cudaGetSymbolAddress((void**)&qkv,  g_qkv);
    cudaGetSymbolAddress((void**)&attn, g_attn);
    cudaGetSymbolAddress((void**)&t1,   g_t1);
    cudaGetSymbolAddress((void**)&t2,   g_t2);
    cudaGetSymbolAddress((void**)&hid,  g_hid);
    cudaGetSymbolAddress((void**)&sf1,  g_sf1);
    cudaGetSymbolAddress((void**)&filt, g_filt);
    cudaGetSymbolAddress((void**)&fus,  g_fus);
    cudaGetSymbolAddress((void**)&d1,   g_d1);

    const int M = MTOK;
    auto blocks = [](long total, int thr) { return (int)((total + thr - 1) / thr); };

    // ---- encoder ----
    im2col_k<<<blocks((long)M * 3 * 9, 256), 256>>>(x, col, 3, 1);
    gemm_cfgB(col, enc_w1, enc_b1, bufA, M, 64, 27, 1);           // relu
    im2col_k<<<blocks((long)M * 64 * 9, 256), 256>>>(bufA, col, 64, 0);
    gemm_cfgB2(col, enc_w2, enc_b2, t, M, 64, 576, 1);            // tokens

    // ---- transformer ----
    gemm_cfgB(t, in_pw, in_pb, qkv, M, 192, 64, 0);
    attn_k<<<blocks((long)HWc * NHc, 256), 256>>>(qkv, attn);
    gemm_cfgB2(attn, out_pw, out_pb, bufA, M, 64, 64, 0);
    ln_res_k<<<blocks((long)M * 32, 256), 256>>>(t, bufA, ln1_g, ln1_b, t1);
    gemm_cfgA(t1, ffn_w1, ffn_b1, hid, M, DFFc, 64, 1);           // FFN up + relu
    gemm_cfgB2(hid, ffn_w2, ffn_b2, bufA, M, 64, DFFc, 0);        // FFN down
    ln_res_k<<<blocks((long)M * 32, 256), 256>>>(t1, bufA, ln2_g, ln2_b, t2);

    // ---- spatial filter branch ----
    im2col_k<<<blocks((long)M * 64 * 9, 256), 256>>>(t2, col, 64, 0);
    gemm_cfgC(col, sf_w1, sf_b1, sf1, M, 32, 576, 0);
    im2col_k<<<blocks((long)M * 32 * 9, 256), 256>>>(sf1, col, 32, 0);
    gemm_cfgD(col, sf_w2, sf_b2, filt, M, 9, 288, 0);
    fuse_k<<<blocks((long)M, 256), 256>>>(x, filt, fus);

    // ---- decoder ----
    im2col_k<<<blocks((long)M * 1 * 9, 256), 256>>>(fus, col, 1, 0);
    gemm_cfgB(col, dec_w1, dec_b1, d1, M, 64, 9, 1);
    im2col_k<<<blocks((long)M * 64 * 9, 256), 256>>>(d1, col, 64, 0);
    gemm_cfgD(col, dec_w2, dec_b2, out, M, 1, 576, 2);            // sigmoid
}

// round 4
// speedup vs baseline: 2.3341x; 1.4491x over previous
#include <cuda_runtime.h>
#include <mma.h>
#include <cstdint>
#include <math.h>

using namespace nvcuda;

#define Hc   224
#define Wc   224
#define HWc  (Hc * Wc)       // 50176
#define Bc   2
#define MTOK (Bc * HWc)      // 100352
#define Ec   64
#define NHc  4
#define DHc  16
#define DFFc 2048

// ---------------- scratch (static device globals; no allocs) ----------------
__device__ float g_col [MTOK * 576];
__device__ float g_bufA[MTOK * 64];
__device__ float g_t   [MTOK * 64];
__device__ float g_qkv [MTOK * 192];
__device__ float g_attn[MTOK * 64];
__device__ float g_t1  [MTOK * 64];
__device__ float g_t2  [MTOK * 64];
__device__ float g_hid [MTOK * DFFc];
__device__ float g_sf1 [MTOK * 32];
__device__ float g_filt[MTOK * 9];
__device__ float g_fus [MTOK];
__device__ float g_d1  [MTOK * 64];

// ================= WMMA tf32 GEMM =================
// C[M,N] = act(A[M,K] @ W[N,K]^T + bias[N]); M multiple of 128.
// act: 0=none 1=relu 2=sigmoid
#define BM 128
#define BN 64
#define BK 32
#define SA 40          // A smem row stride (floats); 160B = 16B multiple
#define SBs 40         // B smem per-n stride (floats)
#define SE 68          // epilogue smem row stride; 272B = 16B multiple

__global__ void __launch_bounds__(256)
wmma_gemm(const float* __restrict__ A, const float* __restrict__ W,
          const float* __restrict__ bias, float* __restrict__ C,
          int M, int N, int K, int act) {
    __shared__ float sm[BM * SE];            // 8704 floats; unioned usage
    float* As = sm;                          // BM*SA = 5120
    float* Bs = sm + BM * SA;                // BN*SBs = 2560

    const int tid = threadIdx.x;
    const int warp = tid >> 5;
    const int wm = warp >> 1;                // 0..3 (M dir, 32 rows each)
    const int wn = warp & 1;                 // 0..1 (N dir, 32 cols each)
    const size_t m0 = (size_t)blockIdx.y * BM;
    const int n0 = blockIdx.x * BN;

    wmma::fragment<wmma::accumulator, 16, 16, 8, float> acc[2][2];
#pragma unroll
    for (int i = 0; i < 2; i++)
#pragma unroll
        for (int j = 0; j < 2; j++) wmma::fill_fragment(acc[i][j], 0.f);

    const bool k4 = ((K & 3) == 0);

    for (int k0 = 0; k0 < K; k0 += BK) {
        // ---- stage A tile: 128 x 32 ----
#pragma unroll
        for (int i = tid; i < BM * 8; i += 256) {
            int row = i >> 3, q = i & 7;
            int gk = k0 + q * 4;
            float4 v = make_float4(0.f, 0.f, 0.f, 0.f);
            const float* p = A + (m0 + row) * K + gk;
            if (k4 && gk + 4 <= K) {
                v = *(const float4*)p;
            } else if (gk < K) {
                v.x = p[0];
                if (gk + 1 < K) v.y = p[1];
                if (gk + 2 < K) v.z = p[2];
                if (gk + 3 < K) v.w = p[3];
            }
            *(float4*)&As[row * SA + q * 4] = v;
        }
        // ---- stage W tile: 64 (n) x 32 (k), Bs[n][k] ----
#pragma unroll
        for (int i = tid; i < BN * 8; i += 256) {
            int n = i >> 3, q = i & 7;
            int gn = n0 + n, gk = k0 + q * 4;
            float4 v = make_float4(0.f, 0.f, 0.f, 0.f);
            if (gn < N) {
                const float* p = W + (size_t)gn * K + gk;
                if (k4 && gk + 4 <= K) {
                    v = *(const float4*)p;
                } else if (gk < K) {
                    v.x = p[0];
                    if (gk + 1 < K) v.y = p[1];
                    if (gk + 2 < K) v.z = p[2];
                    if (gk + 3 < K) v.w = p[3];
                }
            }
            *(float4*)&Bs[n * SBs + q * 4] = v;
        }
        __syncthreads();

#pragma unroll
        for (int ks = 0; ks < 4; ks++) {
            wmma::fragment<wmma::matrix_a, 16, 16, 8, wmma::precision::tf32, wmma::row_major> a[2];
            wmma::fragment<wmma::matrix_b, 16, 16, 8, wmma::precision::tf32, wmma::col_major> b[2];
#pragma unroll
            for (int i = 0; i < 2; i++) {
                wmma::load_matrix_sync(a[i], &As[(wm * 32 + i * 16) * SA + ks * 8], SA);
#pragma unroll
                for (int e = 0; e < a[i].num_elements; e++)
                    a[i].x[e] = wmma::__float_to_tf32(a[i].x[e]);
            }
#pragma unroll
            for (int j = 0; j < 2; j++) {
                wmma::load_matrix_sync(b[j], &Bs[(wn * 32 + j * 16) * SBs + ks * 8], SBs);
#pragma unroll
                for (int e = 0; e < b[j].num_elements; e++)
                    b[j].x[e] = wmma::__float_to_tf32(b[j].x[e]);
            }
#pragma unroll
            for (int i = 0; i < 2; i++)
#pragma unroll
                for (int j = 0; j < 2; j++)
                    wmma::mma_sync(acc[i][j], a[i], b[j], acc[i][j]);
        }
        __syncthreads();
    }

    // ---- epilogue: fragments -> smem -> bias/act -> global ----
#pragma unroll
    for (int i = 0; i < 2; i++)
#pragma unroll
        for (int j = 0; j < 2; j++)
            wmma::store_matrix_sync(&sm[(wm * 32 + i * 16) * SE + wn * 32 + j * 16],
                                    acc[i][j], SE, wmma::mem_row_major);
    __syncthreads();

    for (int i = tid; i < BM * BN; i += 256) {
        int r = i / BN, c = i % BN;
        int gn = n0 + c;
        if (gn >= N) continue;
        float v = sm[r * SE + c] + bias[gn];
        if (act == 1) v = fmaxf(v, 0.f);
        else if (act == 2) v = 1.f / (1.f + expf(-v));
        C[(m0 + r) * N + gn] = v;
    }
}

static void run_gemm(const float* A, const float* W, const float* b, float* C,
                     int M, int N, int K, int act) {
    dim3 g((N + BN - 1) / BN, M / BM);
    wmma_gemm<<<g, 256>>>(A, W, b, C, M, N, K, act);
}

// ---------------- im2col: 3x3, pad 1, stride 1 ----------------
__global__ void im2col_k(const float* __restrict__ src, float* __restrict__ dst,
                         int Cin, int nchw) {
    long tid = (long)blockIdx.x * blockDim.x + threadIdx.x;
    long total = (long)MTOK * Cin * 9;
    if (tid >= total) return;
    int kk = (int)(tid % 9);
    long t2 = tid / 9;
    int ci = (int)(t2 % Cin);
    int m  = (int)(t2 / Cin);
    int b = m / HWc, pix = m % HWc;
    int y = pix / Wc, x = pix % Wc;
    int ky = kk / 3, kx = kk % 3;
    int py = y + ky - 1, px = x + kx - 1;
    float v = 0.f;
    if (py >= 0 && py < Hc && px >= 0 && px < Wc) {
        if (nchw) v = src[((size_t)(b * Cin + ci) * HWc) + py * Wc + px];
        else      v = src[((size_t)(b * HWc + py * Wc + px)) * Cin + ci];
    }
    dst[(size_t)m * (Cin * 9) + ci * 9 + kk] = v;
}

// ---------------- attention ----------------
__global__ void attn_k(const float* __restrict__ qkv, float* __restrict__ out) {
    int idx = blockIdx.x * blockDim.x + threadIdx.x;
    if (idx >= HWc * NHc) return;
    int n = idx / NHc, h = idx % NHc;
    const float* r0 = qkv + (size_t)n * 192 + h * DHc;
    const float* r1 = qkv + (size_t)(HWc + n) * 192 + h * DHc;
    const float *q0 = r0, *k0 = r0 + 64, *v0 = r0 + 128;
    const float *q1 = r1, *k1 = r1 + 64, *v1 = r1 + 128;
    float s00 = 0, s01 = 0, s10 = 0, s11 = 0;
#pragma unroll
    for (int d = 0; d < DHc; d++) {
        float a = q0[d], b = q1[d], c = k0[d], e = k1[d];
        s00 += a * c; s01 += a * e; s10 += b * c; s11 += b * e;
    }
    const float sc = 0.25f;
    s00 *= sc; s01 *= sc; s10 *= sc; s11 *= sc;
    float m0 = fmaxf(s00, s01);
    float e00 = expf(s00 - m0), e01 = expf(s01 - m0);
    float p00 = e00 / (e00 + e01), p01 = e01 / (e00 + e01);
    float m1 = fmaxf(s10, s11);
    float e10 = expf(s10 - m1), e11 = expf(s11 - m1);
    float p10 = e10 / (e10 + e11), p11 = e11 / (e10 + e11);
    float* o0 = out + (size_t)n * 64 + h * DHc;
    float* o1 = out + (size_t)(HWc + n) * 64 + h * DHc;
#pragma unroll
    for (int d = 0; d < DHc; d++) {
        o0[d] = p00 * v0[d] + p01 * v1[d];
        o1[d] = p10 * v0[d] + p11 * v1[d];
    }
}

// ---------------- residual + LayerNorm (warp per token) ----------------
__global__ void ln_res_k(const float* __restrict__ a, const float* __restrict__ b,
                         const float* __restrict__ g, const float* __restrict__ be,
                         float* __restrict__ out) {
    int gt = blockIdx.x * blockDim.x + threadIdx.x;
    int warp = gt / 32, lane = gt % 32;
    if (warp >= MTOK) return;
    size_t base = (size_t)warp * 64;
    float x0 = a[base + lane] + b[base + lane];
    float x1 = a[base + 32 + lane] + b[base + 32 + lane];
    float s = x0 + x1;
#pragma unroll
    for (int o = 16; o > 0; o >>= 1) s += __shfl_xor_sync(0xffffffffu, s, o);
    float mu = s * (1.f / 64.f);
    float c0 = x0 - mu, c1 = x1 - mu;
    float sq = c0 * c0 + c1 * c1;
#pragma unroll
    for (int o = 16; o > 0; o >>= 1) sq += __shfl_xor_sync(0xffffffffu, sq, o);
    float r = rsqrtf(sq * (1.f / 64.f) + 1e-5f);
    out[base + lane]      = g[lane] * c0 * r + be[lane];
    out[base + 32 + lane] = g[lane + 32] * c1 * r + be[lane + 32];
}

// ---------------- per-pixel 3x3 adaptive filter ----------------
__global__ void fuse_k(const float* __restrict__ xin, const float* __restrict__ filt,
                       float* __restrict__ out) {
    int m = blockIdx.x * blockDim.x + threadIdx.x;
    if (m >= MTOK) return;
    int b = m / HWc, pix = m % HWc;
    int y = pix / Wc, x = pix % Wc;
    const float* xb = xin + (size_t)b * 3 * HWc;
    float acc = 0.f;
#pragma unroll
    for (int u = 0; u < 3; u++) {
#pragma unroll
        for (int v = 0; v < 3; v++) {
            int py = y + u - 1, px = x + v - 1;
            if (py < 0 || py >= Hc || px < 0 || px >= Wc) continue;
            int p = py * Wc + px;
            float s = xb[p] + xb[HWc + p] + xb[2 * HWc + p];
            acc += filt[(size_t)m * 9 + u * 3 + v] * s;
        }
    }
    out[m] = acc;
}

extern "C" void kernel_launch(void* const* d_in, const int* in_sizes, int n_in,
                              void* d_out, int out_size) {
    const float* x        = (const float*)d_in[0];
    const float* enc_w1   = (const float*)d_in[1];
    const float* enc_b1   = (const float*)d_in[2];
    const float* enc_w2   = (const float*)d_in[3];
    const float* enc_b2   = (const float*)d_in[4];
    const float* in_pw    = (const float*)d_in[5];
    const float* in_pb    = (const float*)d_in[6];
    const float* out_pw   = (const float*)d_in[7];
    const float* out_pb   = (const float*)d_in[8];
    const float* ln1_g    = (const float*)d_in[9];
    const float* ln1_b    = (const float*)d_in[10];
    const float* ffn_w1   = (const float*)d_in[11];
    const float* ffn_b1   = (const float*)d_in[12];
    const float* ffn_w2   = (const float*)d_in[13];
    const float* ffn_b2   = (const float*)d_in[14];
    const float* ln2_g    = (const float*)d_in[15];
    const float* ln2_b    = (const float*)d_in[16];
    const float* sf_w1    = (const float*)d_in[17];
    const float* sf_b1    = (const float*)d_in[18];
    const float* sf_w2    = (const float*)d_in[19];
    const float* sf_b2    = (const float*)d_in[20];
    const float* dec_w1   = (const float*)d_in[21];
    const float* dec_b1   = (const float*)d_in[22];
    const float* dec_w2   = (const float*)d_in[23];
    const float* dec_b2   = (const float*)d_in[24];
    float* out = (float*)d_out;

    float *col, *bufA, *t, *qkv, *attn, *t1, *t2, *hid, *sf1, *filt, *fus, *d1;
    cudaGetSymbolAddress((void**)&col,  g_col);
    cudaGetSymbolAddress((void**)&bufA, g_bufA);
    cudaGetSymbolAddress((void**)&t,    g_t);
    cudaGetSymbolAddress((void**)&qkv,  g_qkv);
    cudaGetSymbolAddress((void**)&attn, g_attn);
    cudaGetSymbolAddress((void**)&t1,   g_t1);
    cudaGetSymbolAddress((void**)&t2,   g_t2);
    cudaGetSymbolAddress((void**)&hid,  g_hid);
    cudaGetSymbolAddress((void**)&sf1,  g_sf1);
    cudaGetSymbolAddress((void**)&filt, g_filt);
    cudaGetSymbolAddress((void**)&fus,  g_fus);
    cudaGetSymbolAddress((void**)&d1,   g_d1);

    const int M = MTOK;
    auto blocks = [](long total, int thr) { return (int)((total + thr - 1) / thr); };

    // ---- encoder ----
    im2col_k<<<blocks((long)M * 3 * 9, 256), 256>>>(x, col, 3, 1);
    run_gemm(col, enc_w1, enc_b1, bufA, M, 64, 27, 1);            // relu
    im2col_k<<<blocks((long)M * 64 * 9, 256), 256>>>(bufA, col, 64, 0);
    run_gemm(col, enc_w2, enc_b2, t, M, 64, 576, 1);              // tokens

    // ---- transformer ----
    run_gemm(t, in_pw, in_pb, qkv, M, 192, 64, 0);
    attn_k<<<blocks((long)HWc * NHc, 256), 256>>>(qkv, attn);
    run_gemm(attn, out_pw, out_pb, bufA, M, 64, 64, 0);
    ln_res_k<<<blocks((long)M * 32, 256), 256>>>(t, bufA, ln1_g, ln1_b, t1);
    run_gemm(t1, ffn_w1, ffn_b1, hid, M, DFFc, 64, 1);            // FFN up + relu
    run_gemm(hid, ffn_w2, ffn_b2, bufA, M, 64, DFFc, 0);          // FFN down
    ln_res_k<<<blocks((long)M * 32, 256), 256>>>(t1, bufA, ln2_g, ln2_b, t2);

    // ---- spatial filter branch ----
    im2col_k<<<blocks((long)M * 64 * 9, 256), 256>>>(t2, col, 64, 0);
    run_gemm(col, sf_w1, sf_b1, sf1, M, 32, 576, 0);
    im2col_k<<<blocks((long)M * 32 * 9, 256), 256>>>(sf1, col, 32, 0);
    run_gemm(col, sf_w2, sf_b2, filt, M, 9, 288, 0);
    fuse_k<<<blocks((long)M, 256), 256>>>(x, filt, fus);

    // ---- decoder ----
    im2col_k<<<blocks((long)M * 1 * 9, 256), 256>>>(fus, col, 1, 0);
    run_gemm(col, dec_w1, dec_b1, d1, M, 64, 9, 1);
    im2col_k<<<blocks((long)M * 64 * 9, 256), 256>>>(d1, col, 64, 0);
    run_gemm(col, dec_w2, dec_b2, out, M, 1, 576, 2);             // sigmoid
}

// round 6
// speedup vs baseline: 3.4399x; 1.4738x over previous
#include <cuda_runtime.h>
#include <mma.h>
#include <cstdint>
#include <math.h>

using namespace nvcuda;

#define Hc   224
#define Wc   224
#define HWc  (Hc * Wc)       // 50176
#define Bc   2
#define MTOK (Bc * HWc)      // 100352
#define Ec   64
#define NHc  4
#define DHc  16
#define DFFc 2048

// ---------------- scratch (static device globals; no allocs) ----------------
__device__ float g_col [MTOK * 27];      // im2col scratch (enc1 K=27, dec1 K=9)
__device__ float g_bufA[MTOK * 64];
__device__ float g_t   [MTOK * 64];
__device__ float g_qkv [MTOK * 192];
__device__ float g_attn[MTOK * 64];
__device__ float g_t1  [MTOK * 64];
__device__ float g_t2  [MTOK * 64];
__device__ float g_sf1 [MTOK * 32];
__device__ float g_filt[MTOK * 9];
__device__ float g_fus [MTOK];
__device__ float g_d1  [MTOK * 64];
__device__ float g_wr  [64 * 576 + 32 * 576 + 9 * 288 + 1 * 576];  // reordered conv weights

__device__ __forceinline__ float to_tf32(float x) {
    uint32_t r;
    asm("cvt.rna.tf32.f32 %0, %1;" : "=r"(r) : "f"(x));
    return __uint_as_float(r);
}
__device__ __forceinline__ float4 to_tf32_4(float4 v) {
    return make_float4(to_tf32(v.x), to_tf32(v.y), to_tf32(v.z), to_tf32(v.w));
}

#define SA 36          // 32-wide k tiles: 144B stride
#define SE 68          // 64-wide epilogue/hidden tiles: 272B stride
#define FSA 72         // 64-wide k tiles in ffn (>= 64!): 288B stride
#define BM 128
#define BN 64
#define BK 32

// ================= WMMA tf32 GEMM (dense A) =================
// C[M,N] = act(A[M,K] @ W[N,K]^T + bias[N]); M multiple of 128.
__global__ void __launch_bounds__(256)
wmma_gemm(const float* __restrict__ A, const float* __restrict__ W,
          const float* __restrict__ bias, float* __restrict__ C,
          int N, int K, int act) {
    __shared__ float sm[BM * SE];            // 8704 floats, unioned
    float* As = sm;                          // 128*36 = 4608
    float* Bs = sm + BM * SA;                // 64*36  = 2304

    const int tid = threadIdx.x;
    const int warp = tid >> 5;
    const int wm = warp >> 1, wn = warp & 1;
    const size_t m0 = (size_t)blockIdx.y * BM;
    const int n0 = blockIdx.x * BN;
    const bool k4 = ((K & 3) == 0);

    wmma::fragment<wmma::accumulator, 16, 16, 8, float> acc[2][2];
#pragma unroll
    for (int i = 0; i < 2; i++)
#pragma unroll
        for (int j = 0; j < 2; j++) wmma::fill_fragment(acc[i][j], 0.f);

    for (int k0 = 0; k0 < K; k0 += BK) {
#pragma unroll
        for (int i = tid; i < BM * 8; i += 256) {
            int row = i >> 3, q = i & 7;
            int gk = k0 + q * 4;
            float4 v = make_float4(0.f, 0.f, 0.f, 0.f);
            const float* p = A + (m0 + row) * K + gk;
            if (k4 && gk + 4 <= K) v = *(const float4*)p;
            else if (gk < K) {
                v.x = p[0];
                if (gk + 1 < K) v.y = p[1];
                if (gk + 2 < K) v.z = p[2];
                if (gk + 3 < K) v.w = p[3];
            }
            *(float4*)&As[row * SA + q * 4] = to_tf32_4(v);
        }
#pragma unroll
        for (int i = tid; i < BN * 8; i += 256) {
            int n = i >> 3, q = i & 7;
            int gn = n0 + n, gk = k0 + q * 4;
            float4 v = make_float4(0.f, 0.f, 0.f, 0.f);
            if (gn < N) {
                const float* p = W + (size_t)gn * K + gk;
                if (k4 && gk + 4 <= K) v = *(const float4*)p;
                else if (gk < K) {
                    v.x = p[0];
                    if (gk + 1 < K) v.y = p[1];
                    if (gk + 2 < K) v.z = p[2];
                    if (gk + 3 < K) v.w = p[3];
                }
            }
            *(float4*)&Bs[n * SA + q * 4] = to_tf32_4(v);
        }
        __syncthreads();
#pragma unroll
        for (int ks = 0; ks < 4; ks++) {
            wmma::fragment<wmma::matrix_a, 16, 16, 8, wmma::precision::tf32, wmma::row_major> a[2];
            wmma::fragment<wmma::matrix_b, 16, 16, 8, wmma::precision::tf32, wmma::col_major> b[2];
#pragma unroll
            for (int i = 0; i < 2; i++)
                wmma::load_matrix_sync(a[i], &As[(wm * 32 + i * 16) * SA + ks * 8], SA);
#pragma unroll
            for (int j = 0; j < 2; j++)
                wmma::load_matrix_sync(b[j], &Bs[(wn * 32 + j * 16) * SA + ks * 8], SA);
#pragma unroll
            for (int i = 0; i < 2; i++)
#pragma unroll
                for (int j = 0; j < 2; j++)
                    wmma::mma_sync(acc[i][j], a[i], b[j], acc[i][j]);
        }
        __syncthreads();
    }

#pragma unroll
    for (int i = 0; i < 2; i++)
#pragma unroll
        for (int j = 0; j < 2; j++)
            wmma::store_matrix_sync(&sm[(wm * 32 + i * 16) * SE + wn * 32 + j * 16],
                                    acc[i][j], SE, wmma::mem_row_major);
    __syncthreads();
    for (int i = tid; i < BM * BN; i += 256) {
        int r = i / BN, c = i % BN;
        int gn = n0 + c;
        if (gn >= N) continue;
        float v = sm[r * SE + c] + bias[gn];
        if (act == 1) v = fmaxf(v, 0.f);
        else if (act == 2) v = 1.f / (1.f + expf(-v));
        C[(m0 + r) * N + gn] = v;
    }
}

// ================= implicit-im2col conv GEMM =================
// src: channel-last activation [MTOK, Cin]; weights reordered k = kk*Cin+ci.
// Cin multiple of 32. K = 9*Cin.
__global__ void __launch_bounds__(256)
conv_gemm(const float* __restrict__ src, int Cin,
          const float* __restrict__ Wr, const float* __restrict__ bias,
          float* __restrict__ C, int N, int act) {
    __shared__ float sm[BM * SE];
    float* As = sm;
    float* Bs = sm + BM * SA;

    const int tid = threadIdx.x;
    const int warp = tid >> 5;
    const int wm = warp >> 1, wn = warp & 1;
    const size_t m0 = (size_t)blockIdx.y * BM;
    const int n0 = blockIdx.x * BN;
    const int K = 9 * Cin;
    const int chunks = K / BK;

    wmma::fragment<wmma::accumulator, 16, 16, 8, float> acc[2][2];
#pragma unroll
    for (int i = 0; i < 2; i++)
#pragma unroll
        for (int j = 0; j < 2; j++) wmma::fill_fragment(acc[i][j], 0.f);

    for (int c = 0; c < chunks; c++) {
        const int k0 = c * BK;
        const int kk = k0 / Cin;
        const int ci0 = k0 % Cin;
        const int ky = kk / 3 - 1, kx = kk % 3 - 1;
#pragma unroll
        for (int i = tid; i < BM * 8; i += 256) {
            int row = i >> 3, q = i & 7;
            int m = (int)m0 + row;
            int b = m / HWc, pix = m % HWc;
            int y = pix / Wc, x = pix % Wc;
            int py = y + ky, px = x + kx;
            float4 v = make_float4(0.f, 0.f, 0.f, 0.f);
            if (py >= 0 && py < Hc && px >= 0 && px < Wc)
                v = *(const float4*)&src[((size_t)b * HWc + py * Wc + px) * Cin + ci0 + q * 4];
            *(float4*)&As[row * SA + q * 4] = to_tf32_4(v);
        }
#pragma unroll
        for (int i = tid; i < BN * 8; i += 256) {
            int n = i >> 3, q = i & 7;
            int gn = n0 + n;
            float4 v = make_float4(0.f, 0.f, 0.f, 0.f);
            if (gn < N) v = *(const float4*)&Wr[(size_t)gn * K + k0 + q * 4];
            *(float4*)&Bs[n * SA + q * 4] = to_tf32_4(v);
        }
        __syncthreads();
#pragma unroll
        for (int ks = 0; ks < 4; ks++) {
            wmma::fragment<wmma::matrix_a, 16, 16, 8, wmma::precision::tf32, wmma::row_major> a[2];
            wmma::fragment<wmma::matrix_b, 16, 16, 8, wmma::precision::tf32, wmma::col_major> b[2];
#pragma unroll
            for (int i = 0; i < 2; i++)
                wmma::load_matrix_sync(a[i], &As[(wm * 32 + i * 16) * SA + ks * 8], SA);
#pragma unroll
            for (int j = 0; j < 2; j++)
                wmma::load_matrix_sync(b[j], &Bs[(wn * 32 + j * 16) * SA + ks * 8], SA);
#pragma unroll
            for (int i = 0; i < 2; i++)
#pragma unroll
                for (int j = 0; j < 2; j++)
                    wmma::mma_sync(acc[i][j], a[i], b[j], acc[i][j]);
        }
        __syncthreads();
    }

#pragma unroll
    for (int i = 0; i < 2; i++)
#pragma unroll
        for (int j = 0; j < 2; j++)
            wmma::store_matrix_sync(&sm[(wm * 32 + i * 16) * SE + wn * 32 + j * 16],
                                    acc[i][j], SE, wmma::mem_row_major);
    __syncthreads();
    for (int i = tid; i < BM * BN; i += 256) {
        int r = i / BN, col = i % BN;
        int gn = n0 + col;
        if (gn >= N) continue;
        float v = sm[r * SE + col] + bias[gn];
        if (act == 1) v = fmaxf(v, 0.f);
        else if (act == 2) v = 1.f / (1.f + expf(-v));
        C[(m0 + r) * N + gn] = v;
    }
}

// ================= fused FFN: out = relu(A@W1^T+b1) @ W2^T + b2 =================
// smem: As 128*FSA, W1s 64*FSA, W2s 64*FSA, Hs 128*SE
__global__ void __launch_bounds__(256)
ffn_fused(const float* __restrict__ A, const float* __restrict__ W1,
          const float* __restrict__ B1, const float* __restrict__ W2,
          const float* __restrict__ B2, float* __restrict__ Cout) {
    extern __shared__ float fsm[];
    float* As  = fsm;                        // 128*72 = 9216
    float* W1s = As + 128 * FSA;             // 64*72  = 4608
    float* W2s = W1s + 64 * FSA;             // 4608
    float* Hs  = W2s + 64 * FSA;             // 128*68 = 8704
    const int tid = threadIdx.x;
    const int warp = tid >> 5;
    const int wm = warp >> 1, wn = warp & 1;
    const size_t m0 = (size_t)blockIdx.x * 128;

    // stage A (128 x 64) once
#pragma unroll
    for (int i = tid; i < 128 * 16; i += 256) {
        int row = i >> 4, q = i & 15;
        float4 v = *(const float4*)&A[(m0 + row) * 64 + q * 4];
        *(float4*)&As[row * FSA + q * 4] = to_tf32_4(v);
    }

    wmma::fragment<wmma::accumulator, 16, 16, 8, float> out[2][2];
#pragma unroll
    for (int i = 0; i < 2; i++)
#pragma unroll
        for (int j = 0; j < 2; j++) wmma::fill_fragment(out[i][j], 0.f);

    for (int c = 0; c < 32; c++) {
#pragma unroll
        for (int i = tid; i < 64 * 16; i += 256) {
            int n = i >> 4, q = i & 15;
            float4 v = *(const float4*)&W1[((size_t)c * 64 + n) * 64 + q * 4];
            *(float4*)&W1s[n * FSA + q * 4] = to_tf32_4(v);
        }
#pragma unroll
        for (int i = tid; i < 64 * 16; i += 256) {
            int o = i >> 4, q = i & 15;
            float4 v = *(const float4*)&W2[(size_t)o * DFFc + c * 64 + q * 4];
            *(float4*)&W2s[o * FSA + q * 4] = to_tf32_4(v);
        }
        __syncthreads();

        // hid = A @ W1c^T
        wmma::fragment<wmma::accumulator, 16, 16, 8, float> hacc[2][2];
#pragma unroll
        for (int i = 0; i < 2; i++)
#pragma unroll
            for (int j = 0; j < 2; j++) wmma::fill_fragment(hacc[i][j], 0.f);
#pragma unroll
        for (int ks = 0; ks < 8; ks++) {
            wmma::fragment<wmma::matrix_a, 16, 16, 8, wmma::precision::tf32, wmma::row_major> a[2];
            wmma::fragment<wmma::matrix_b, 16, 16, 8, wmma::precision::tf32, wmma::col_major> b[2];
#pragma unroll
            for (int i = 0; i < 2; i++)
                wmma::load_matrix_sync(a[i], &As[(wm * 32 + i * 16) * FSA + ks * 8], FSA);
#pragma unroll
            for (int j = 0; j < 2; j++)
                wmma::load_matrix_sync(b[j], &W1s[(wn * 32 + j * 16) * FSA + ks * 8], FSA);
#pragma unroll
            for (int i = 0; i < 2; i++)
#pragma unroll
                for (int j = 0; j < 2; j++)
                    wmma::mma_sync(hacc[i][j], a[i], b[j], hacc[i][j]);
        }
#pragma unroll
        for (int i = 0; i < 2; i++)
#pragma unroll
            for (int j = 0; j < 2; j++)
                wmma::store_matrix_sync(&Hs[(wm * 32 + i * 16) * SE + wn * 32 + j * 16],
                                        hacc[i][j], SE, wmma::mem_row_major);
        __syncthreads();

        // bias + relu + tf32 in place
#pragma unroll
        for (int i = tid; i < 128 * 64; i += 256) {
            int r = i >> 6, col = i & 63;
            float v = Hs[r * SE + col] + __ldg(&B1[c * 64 + col]);
            Hs[r * SE + col] = to_tf32(fmaxf(v, 0.f));
        }
        __syncthreads();

        // out += hid @ W2c^T
#pragma unroll
        for (int ks = 0; ks < 8; ks++) {
            wmma::fragment<wmma::matrix_a, 16, 16, 8, wmma::precision::tf32, wmma::row_major> a[2];
            wmma::fragment<wmma::matrix_b, 16, 16, 8, wmma::precision::tf32, wmma::col_major> b[2];
#pragma unroll
            for (int i = 0; i < 2; i++)
                wmma::load_matrix_sync(a[i], &Hs[(wm * 32 + i * 16) * SE + ks * 8], SE);
#pragma unroll
            for (int j = 0; j < 2; j++)
                wmma::load_matrix_sync(b[j], &W2s[(wn * 32 + j * 16) * FSA + ks * 8], FSA);
#pragma unroll
            for (int i = 0; i < 2; i++)
#pragma unroll
                for (int j = 0; j < 2; j++)
                    wmma::mma_sync(out[i][j], a[i], b[j], out[i][j]);
        }
        __syncthreads();
    }

#pragma unroll
    for (int i = 0; i < 2; i++)
#pragma unroll
        for (int j = 0; j < 2; j++)
            wmma::store_matrix_sync(&Hs[(wm * 32 + i * 16) * SE + wn * 32 + j * 16],
                                    out[i][j], SE, wmma::mem_row_major);
    __syncthreads();
#pragma unroll
    for (int i = tid; i < 128 * 64; i += 256) {
        int r = i >> 6, col = i & 63;
        Cout[(m0 + r) * 64 + col] = Hs[r * SE + col] + B2[col];
    }
}
#define FFN_SMEM ((128 * FSA + 2 * 64 * FSA + 128 * SE) * 4)

// ---------------- weight reorder: k = ci*9+kk -> kk*Cin+ci ----------------
__global__ void reorder_w(const float* __restrict__ in, float* __restrict__ out,
                          int O, int Cin) {
    int K = Cin * 9;
    int i = blockIdx.x * 256 + threadIdx.x;
    if (i >= O * K) return;
    int o = i / K, k = i % K;
    int kk = k / Cin, ci = k % Cin;
    out[(size_t)o * K + k] = in[(size_t)o * K + ci * 9 + kk];
}

// ---------------- im2col (small layers only) ----------------
__global__ void im2col_k(const float* __restrict__ src, float* __restrict__ dst,
                         int Cin, int nchw) {
    long tid = (long)blockIdx.x * blockDim.x + threadIdx.x;
    long total = (long)MTOK * Cin * 9;
    if (tid >= total) return;
    int kk = (int)(tid % 9);
    long t2 = tid / 9;
    int ci = (int)(t2 % Cin);
    int m  = (int)(t2 / Cin);
    int b = m / HWc, pix = m % HWc;
    int y = pix / Wc, x = pix % Wc;
    int ky = kk / 3, kx = kk % 3;
    int py = y + ky - 1, px = x + kx - 1;
    float v = 0.f;
    if (py >= 0 && py < Hc && px >= 0 && px < Wc) {
        if (nchw) v = src[((size_t)(b * Cin + ci) * HWc) + py * Wc + px];
        else      v = src[((size_t)(b * HWc + py * Wc + px)) * Cin + ci];
    }
    dst[(size_t)m * (Cin * 9) + ci * 9 + kk] = v;
}

// ---------------- attention ----------------
__global__ void attn_k(const float* __restrict__ qkv, float* __restrict__ out) {
    int idx = blockIdx.x * blockDim.x + threadIdx.x;
    if (idx >= HWc * NHc) return;
    int n = idx / NHc, h = idx % NHc;
    const float* r0 = qkv + (size_t)n * 192 + h * DHc;
    const float* r1 = qkv + (size_t)(HWc + n) * 192 + h * DHc;
    const float *q0 = r0, *k0 = r0 + 64, *v0 = r0 + 128;
    const float *q1 = r1, *k1 = r1 + 64, *v1 = r1 + 128;
    float s00 = 0, s01 = 0, s10 = 0, s11 = 0;
#pragma unroll
    for (int d = 0; d < DHc; d++) {
        float a = q0[d], b = q1[d], c = k0[d], e = k1[d];
        s00 += a * c; s01 += a * e; s10 += b * c; s11 += b * e;
    }
    const float sc = 0.25f;
    s00 *= sc; s01 *= sc; s10 *= sc; s11 *= sc;
    float m0 = fmaxf(s00, s01);
    float e00 = expf(s00 - m0), e01 = expf(s01 - m0);
    float p00 = e00 / (e00 + e01), p01 = e01 / (e00 + e01);
    float m1 = fmaxf(s10, s11);
    float e10 = expf(s10 - m1), e11 = expf(s11 - m1);
    float p10 = e10 / (e10 + e11), p11 = e11 / (e10 + e11);
    float* o0 = out + (size_t)n * 64 + h * DHc;
    float* o1 = out + (size_t)(HWc + n) * 64 + h * DHc;
#pragma unroll
    for (int d = 0; d < DHc; d++) {
        o0[d] = p00 * v0[d] + p01 * v1[d];
        o1[d] = p10 * v0[d] + p11 * v1[d];
    }
}

// ---------------- residual + LayerNorm ----------------
__global__ void ln_res_k(const float* __restrict__ a, const float* __restrict__ b,
                         const float* __restrict__ g, const float* __restrict__ be,
                         float* __restrict__ out) {
    int gt = blockIdx.x * blockDim.x + threadIdx.x;
    int warp = gt / 32, lane = gt % 32;
    if (warp >= MTOK) return;
    size_t base = (size_t)warp * 64;
    float x0 = a[base + lane] + b[base + lane];
    float x1 = a[base + 32 + lane] + b[base + 32 + lane];
    float s = x0 + x1;
#pragma unroll
    for (int o = 16; o > 0; o >>= 1) s += __shfl_xor_sync(0xffffffffu, s, o);
    float mu = s * (1.f / 64.f);
    float c0 = x0 - mu, c1 = x1 - mu;
    float sq = c0 * c0 + c1 * c1;
#pragma unroll
    for (int o = 16; o > 0; o >>= 1) sq += __shfl_xor_sync(0xffffffffu, sq, o);
    float r = rsqrtf(sq * (1.f / 64.f) + 1e-5f);
    out[base + lane]      = g[lane] * c0 * r + be[lane];
    out[base + 32 + lane] = g[lane + 32] * c1 * r + be[lane + 32];
}

// ---------------- per-pixel 3x3 adaptive filter ----------------
__global__ void fuse_k(const float* __restrict__ xin, const float* __restrict__ filt,
                       float* __restrict__ out) {
    int m = blockIdx.x * blockDim.x + threadIdx.x;
    if (m >= MTOK) return;
    int b = m / HWc, pix = m % HWc;
    int y = pix / Wc, x = pix % Wc;
    const float* xb = xin + (size_t)b * 3 * HWc;
    float acc = 0.f;
#pragma unroll
    for (int u = 0; u < 3; u++) {
#pragma unroll
        for (int v = 0; v < 3; v++) {
            int py = y + u - 1, px = x + v - 1;
            if (py < 0 || py >= Hc || px < 0 || px >= Wc) continue;
            int p = py * Wc + px;
            float s = xb[p] + xb[HWc + p] + xb[2 * HWc + p];
            acc += filt[(size_t)m * 9 + u * 3 + v] * s;
        }
    }
    out[m] = acc;
}

static void run_gemm(const float* A, const float* W, const float* b, float* C,
                     int N, int K, int act) {
    dim3 g((N + BN - 1) / BN, MTOK / BM);
    wmma_gemm<<<g, 256>>>(A, W, b, C, N, K, act);
}
static void run_conv(const float* src, int Cin, const float* Wr, const float* b,
                     float* C, int N, int act) {
    dim3 g((N + BN - 1) / BN, MTOK / BM);
    conv_gemm<<<g, 256>>>(src, Cin, Wr, b, C, N, act);
}

extern "C" void kernel_launch(void* const* d_in, const int* in_sizes, int n_in,
                              void* d_out, int out_size) {
    const float* x        = (const float*)d_in[0];
    const float* enc_w1   = (const float*)d_in[1];
    const float* enc_b1   = (const float*)d_in[2];
    const float* enc_w2   = (const float*)d_in[3];
    const float* enc_b2   = (const float*)d_in[4];
    const float* in_pw    = (const float*)d_in[5];
    const float* in_pb    = (const float*)d_in[6];
    const float* out_pw   = (const float*)d_in[7];
    const float* out_pb   = (const float*)d_in[8];
    const float* ln1_g    = (const float*)d_in[9];
    const float* ln1_b    = (const float*)d_in[10];
    const float* ffn_w1   = (const float*)d_in[11];
    const float* ffn_b1   = (const float*)d_in[12];
    const float* ffn_w2   = (const float*)d_in[13];
    const float* ffn_b2   = (const float*)d_in[14];
    const float* ln2_g    = (const float*)d_in[15];
    const float* ln2_b    = (const float*)d_in[16];
    const float* sf_w1    = (const float*)d_in[17];
    const float* sf_b1    = (const float*)d_in[18];
    const float* sf_w2    = (const float*)d_in[19];
    const float* sf_b2    = (const float*)d_in[20];
    const float* dec_w1   = (const float*)d_in[21];
    const float* dec_b1   = (const float*)d_in[22];
    const float* dec_w2   = (const float*)d_in[23];
    const float* dec_b2   = (const float*)d_in[24];
    float* out = (float*)d_out;

    float *col, *bufA, *t, *qkv, *attn, *t1, *t2, *sf1, *filt, *fus, *d1, *wr;
    cudaGetSymbolAddress((void**)&col,  g_col);
    cudaGetSymbolAddress((void**)&bufA, g_bufA);
    cudaGetSymbolAddress((void**)&t,    g_t);
    cudaGetSymbolAddress((void**)&qkv,  g_qkv);
    cudaGetSymbolAddress((void**)&attn, g_attn);
    cudaGetSymbolAddress((void**)&t1,   g_t1);
    cudaGetSymbolAddress((void**)&t2,   g_t2);
    cudaGetSymbolAddress((void**)&sf1,  g_sf1);
    cudaGetSymbolAddress((void**)&filt, g_filt);
    cudaGetSymbolAddress((void**)&fus,  g_fus);
    cudaGetSymbolAddress((void**)&d1,   g_d1);
    cudaGetSymbolAddress((void**)&wr,   g_wr);

    float* wr_enc2 = wr;                         // 64*576
    float* wr_sf1  = wr_enc2 + 64 * 576;         // 32*576
    float* wr_sf2  = wr_sf1 + 32 * 576;          // 9*288
    float* wr_dec2 = wr_sf2 + 9 * 288;           // 1*576

    cudaFuncSetAttribute(ffn_fused, cudaFuncAttributeMaxDynamicSharedMemorySize, FFN_SMEM);

    const int M = MTOK;
    auto blocks = [](long total, int thr) { return (int)((total + thr - 1) / thr); };

    // weight reorders (tiny)
    reorder_w<<<blocks(64 * 576, 256), 256>>>(enc_w2, wr_enc2, 64, 64);
    reorder_w<<<blocks(32 * 576, 256), 256>>>(sf_w1, wr_sf1, 32, 64);
    reorder_w<<<blocks(9 * 288, 256), 256>>>(sf_w2, wr_sf2, 9, 32);
    reorder_w<<<blocks(1 * 576, 256), 256>>>(dec_w2, wr_dec2, 1, 64);

    // ---- encoder ----
    im2col_k<<<blocks((long)M * 3 * 9, 256), 256>>>(x, col, 3, 1);
    run_gemm(col, enc_w1, enc_b1, bufA, 64, 27, 1);               // relu
    run_conv(bufA, 64, wr_enc2, enc_b2, t, 64, 1);                // tokens

    // ---- transformer ----
    run_gemm(t, in_pw, in_pb, qkv, 192, 64, 0);
    attn_k<<<blocks((long)HWc * NHc, 256), 256>>>(qkv, attn);
    run_gemm(attn, out_pw, out_pb, bufA, 64, 64, 0);
    ln_res_k<<<blocks((long)M * 32, 256), 256>>>(t, bufA, ln1_g, ln1_b, t1);
    ffn_fused<<<M / 128, 256, FFN_SMEM>>>(t1, ffn_w1, ffn_b1, ffn_w2, ffn_b2, bufA);
    ln_res_k<<<blocks((long)M * 32, 256), 256>>>(t1, bufA, ln2_g, ln2_b, t2);

    // ---- spatial filter branch ----
    run_conv(t2, 64, wr_sf1, sf_b1, sf1, 32, 0);
    run_conv(sf1, 32, wr_sf2, sf_b2, filt, 9, 0);
    fuse_k<<<blocks((long)M, 256), 256>>>(x, filt, fus);

    // ---- decoder ----
    im2col_k<<<blocks((long)M * 1 * 9, 256), 256>>>(fus, col, 1, 0);
    run_gemm(col, dec_w1, dec_b1, d1, 64, 9, 1);
    run_conv(d1, 64, wr_dec2, dec_b2, out, 1, 2);                 // sigmoid
}

// round 7
// speedup vs baseline: 3.4410x; 1.0003x over previous
#include <cuda_runtime.h>
#include <mma.h>
#include <cstdint>
#include <math.h>

using namespace nvcuda;

#define Hc   224
#define Wc   224
#define HWc  (Hc * Wc)       // 50176
#define Bc   2
#define MTOK (Bc * HWc)      // 100352
#define Ec   64
#define NHc  4
#define DHc  16
#define DFFc 2048

// ---------------- scratch (static device globals; no allocs) ----------------
__device__ float g_col [MTOK * 27];
__device__ float g_bufA[MTOK * 64];
__device__ float g_t   [MTOK * 64];
__device__ float g_qkv [MTOK * 192];
__device__ float g_attn[MTOK * 64];
__device__ float g_t1  [MTOK * 64];
__device__ float g_t2  [MTOK * 64];
__device__ float g_sf1 [MTOK * 32];
__device__ float g_filt[MTOK * 9];
__device__ float g_fus [MTOK];
__device__ float g_d1  [MTOK * 64];
__device__ float g_wr  [64 * 576 + 32 * 576 + 9 * 288 + 1 * 576];

__device__ __forceinline__ float to_tf32(float x) {
    uint32_t r;
    asm("cvt.rna.tf32.f32 %0, %1;" : "=r"(r) : "f"(x));
    return __uint_as_float(r);
}
__device__ __forceinline__ float4 to_tf32_4(float4 v) {
    return make_float4(to_tf32(v.x), to_tf32(v.y), to_tf32(v.z), to_tf32(v.w));
}

#define SA 36     // 32-wide k tiles (stride mod 32 = 4 -> 2-way)
#define SE 68     // 64-wide tiles   (stride mod 32 = 4 -> 2-way)
#define BM 128
#define BN 64
#define BK 32
#define GEMM_SMEM ((2 * BM * SA + 2 * BN * SA) * 4)                    // 55296
#define FFN_SMEM  ((128 * SE + 2 * 64 * SE + 2 * 64 * SE + 128 * SE) * 4)  // 139264

// ================= pipelined WMMA tf32 GEMM (dense A) =================
__global__ void __launch_bounds__(256)
wmma_gemm(const float* __restrict__ A, const float* __restrict__ W,
          const float* __restrict__ bias, float* __restrict__ C,
          int N, int K, int act) {
    extern __shared__ float sm[];
    float* AsB = sm;                   // 2 x 128*SA
    float* BsB = sm + 2 * BM * SA;     // 2 x 64*SA

    const int tid = threadIdx.x;
    const int warp = tid >> 5;
    const int wm = warp >> 1, wn = warp & 1;
    const size_t m0 = (size_t)blockIdx.y * BM;
    const int n0 = blockIdx.x * BN;
    const bool k4 = ((K & 3) == 0);
    const int chunks = (K + BK - 1) / BK;

    float4 aR[4], bR[2];

    auto load_glb = [&](int k0) {
#pragma unroll
        for (int u = 0; u < 4; u++) {
            int i = tid + u * 256;
            int row = i >> 3, q = i & 7;
            int gk = k0 + q * 4;
            float4 v = make_float4(0.f, 0.f, 0.f, 0.f);
            const float* p = A + (m0 + row) * K + gk;
            if (k4 && gk + 4 <= K) v = *(const float4*)p;
            else if (gk < K) {
                v.x = p[0];
                if (gk + 1 < K) v.y = p[1];
                if (gk + 2 < K) v.z = p[2];
                if (gk + 3 < K) v.w = p[3];
            }
            aR[u] = v;
        }
#pragma unroll
        for (int u = 0; u < 2; u++) {
            int i = tid + u * 256;
            int n = i >> 3, q = i & 7;
            int gn = n0 + n, gk = k0 + q * 4;
            float4 v = make_float4(0.f, 0.f, 0.f, 0.f);
            if (gn < N) {
                const float* p = W + (size_t)gn * K + gk;
                if (k4 && gk + 4 <= K) v = *(const float4*)p;
                else if (gk < K) {
                    v.x = p[0];
                    if (gk + 1 < K) v.y = p[1];
                    if (gk + 2 < K) v.z = p[2];
                    if (gk + 3 < K) v.w = p[3];
                }
            }
            bR[u] = v;
        }
    };
    auto sts_all = [&](int buf) {
        float* Ab = AsB + buf * BM * SA;
        float* Bb = BsB + buf * BN * SA;
#pragma unroll
        for (int u = 0; u < 4; u++) {
            int i = tid + u * 256;
            int row = i >> 3, q = i & 7;
            *(float4*)&Ab[row * SA + q * 4] = to_tf32_4(aR[u]);
        }
#pragma unroll
        for (int u = 0; u < 2; u++) {
            int i = tid + u * 256;
            int n = i >> 3, q = i & 7;
            *(float4*)&Bb[n * SA + q * 4] = to_tf32_4(bR[u]);
        }
    };

    wmma::fragment<wmma::accumulator, 16, 16, 8, float> acc[2][2];
#pragma unroll
    for (int i = 0; i < 2; i++)
#pragma unroll
        for (int j = 0; j < 2; j++) wmma::fill_fragment(acc[i][j], 0.f);

    load_glb(0);
    sts_all(0);
    __syncthreads();

    for (int c = 0; c < chunks; c++) {
        const int buf = c & 1;
        if (c + 1 < chunks) load_glb((c + 1) * BK);   // overlap with MMAs below
        float* Ab = AsB + buf * BM * SA;
        float* Bb = BsB + buf * BN * SA;
#pragma unroll
        for (int ks = 0; ks < 4; ks++) {
            wmma::fragment<wmma::matrix_a, 16, 16, 8, wmma::precision::tf32, wmma::row_major> a[2];
            wmma::fragment<wmma::matrix_b, 16, 16, 8, wmma::precision::tf32, wmma::col_major> b[2];
#pragma unroll
            for (int i = 0; i < 2; i++)
                wmma::load_matrix_sync(a[i], &Ab[(wm * 32 + i * 16) * SA + ks * 8], SA);
#pragma unroll
            for (int j = 0; j < 2; j++)
                wmma::load_matrix_sync(b[j], &Bb[(wn * 32 + j * 16) * SA + ks * 8], SA);
#pragma unroll
            for (int i = 0; i < 2; i++)
#pragma unroll
                for (int j = 0; j < 2; j++)
                    wmma::mma_sync(acc[i][j], a[i], b[j], acc[i][j]);
        }
        if (c + 1 < chunks) sts_all((c + 1) & 1);     // other buffer: no race
        __syncthreads();
    }

    // epilogue: reuse sm with SE stride
#pragma unroll
    for (int i = 0; i < 2; i++)
#pragma unroll
        for (int j = 0; j < 2; j++)
            wmma::store_matrix_sync(&sm[(wm * 32 + i * 16) * SE + wn * 32 + j * 16],
                                    acc[i][j], SE, wmma::mem_row_major);
    __syncthreads();
    for (int i = tid; i < BM * BN; i += 256) {
        int r = i / BN, c = i % BN;
        int gn = n0 + c;
        if (gn >= N) continue;
        float v = sm[r * SE + c] + bias[gn];
        if (act == 1) v = fmaxf(v, 0.f);
        else if (act == 2) v = 1.f / (1.f + expf(-v));
        C[(m0 + r) * N + gn] = v;
    }
}

// ================= pipelined implicit-im2col conv GEMM =================
// src channel-last [MTOK, Cin]; weights reordered k = kk*Cin+ci; Cin mult of 32.
__global__ void __launch_bounds__(256)
conv_gemm(const float* __restrict__ src, int Cin,
          const float* __restrict__ Wr, const float* __restrict__ bias,
          float* __restrict__ C, int N, int act) {
    extern __shared__ float sm[];
    float* AsB = sm;
    float* BsB = sm + 2 * BM * SA;

    const int tid = threadIdx.x;
    const int warp = tid >> 5;
    const int wm = warp >> 1, wn = warp & 1;
    const size_t m0 = (size_t)blockIdx.y * BM;
    const int n0 = blockIdx.x * BN;
    const int K = 9 * Cin;
    const int chunks = K / BK;

    float4 aR[4], bR[2];

    auto load_glb = [&](int c) {
        const int k0 = c * BK;
        const int kk = k0 / Cin;
        const int ci0 = k0 % Cin;
        const int ky = kk / 3 - 1, kx = kk % 3 - 1;
#pragma unroll
        for (int u = 0; u < 4; u++) {
            int i = tid + u * 256;
            int row = i >> 3, q = i & 7;
            int m = (int)m0 + row;
            int b = m / HWc, pix = m % HWc;
            int y = pix / Wc, x = pix % Wc;
            int py = y + ky, px = x + kx;
            float4 v = make_float4(0.f, 0.f, 0.f, 0.f);
            if (py >= 0 && py < Hc && px >= 0 && px < Wc)
                v = *(const float4*)&src[((size_t)b * HWc + py * Wc + px) * Cin + ci0 + q * 4];
            aR[u] = v;
        }
#pragma unroll
        for (int u = 0; u < 2; u++) {
            int i = tid + u * 256;
            int n = i >> 3, q = i & 7;
            int gn = n0 + n;
            float4 v = make_float4(0.f, 0.f, 0.f, 0.f);
            if (gn < N) v = *(const float4*)&Wr[(size_t)gn * K + k0 + q * 4];
            bR[u] = v;
        }
    };
    auto sts_all = [&](int buf) {
        float* Ab = AsB + buf * BM * SA;
        float* Bb = BsB + buf * BN * SA;
#pragma unroll
        for (int u = 0; u < 4; u++) {
            int i = tid + u * 256;
            int row = i >> 3, q = i & 7;
            *(float4*)&Ab[row * SA + q * 4] = to_tf32_4(aR[u]);
        }
#pragma unroll
        for (int u = 0; u < 2; u++) {
            int i = tid + u * 256;
            int n = i >> 3, q = i & 7;
            *(float4*)&Bb[n * SA + q * 4] = to_tf32_4(bR[u]);
        }
    };

    wmma::fragment<wmma::accumulator, 16, 16, 8, float> acc[2][2];
#pragma unroll
    for (int i = 0; i < 2; i++)
#pragma unroll
        for (int j = 0; j < 2; j++) wmma::fill_fragment(acc[i][j], 0.f);

    load_glb(0);
    sts_all(0);
    __syncthreads();

    for (int c = 0; c < chunks; c++) {
        const int buf = c & 1;
        if (c + 1 < chunks) load_glb(c + 1);
        float* Ab = AsB + buf * BM * SA;
        float* Bb = BsB + buf * BN * SA;
#pragma unroll
        for (int ks = 0; ks < 4; ks++) {
            wmma::fragment<wmma::matrix_a, 16, 16, 8, wmma::precision::tf32, wmma::row_major> a[2];
            wmma::fragment<wmma::matrix_b, 16, 16, 8, wmma::precision::tf32, wmma::col_major> b[2];
#pragma unroll
            for (int i = 0; i < 2; i++)
                wmma::load_matrix_sync(a[i], &Ab[(wm * 32 + i * 16) * SA + ks * 8], SA);
#pragma unroll
            for (int j = 0; j < 2; j++)
                wmma::load_matrix_sync(b[j], &Bb[(wn * 32 + j * 16) * SA + ks * 8], SA);
#pragma unroll
            for (int i = 0; i < 2; i++)
#pragma unroll
                for (int j = 0; j < 2; j++)
                    wmma::mma_sync(acc[i][j], a[i], b[j], acc[i][j]);
        }
        if (c + 1 < chunks) sts_all((c + 1) & 1);
        __syncthreads();
    }

#pragma unroll
    for (int i = 0; i < 2; i++)
#pragma unroll
        for (int j = 0; j < 2; j++)
            wmma::store_matrix_sync(&sm[(wm * 32 + i * 16) * SE + wn * 32 + j * 16],
                                    acc[i][j], SE, wmma::mem_row_major);
    __syncthreads();
    for (int i = tid; i < BM * BN; i += 256) {
        int r = i / BN, col = i % BN;
        int gn = n0 + col;
        if (gn >= N) continue;
        float v = sm[r * SE + col] + bias[gn];
        if (act == 1) v = fmaxf(v, 0.f);
        else if (act == 2) v = 1.f / (1.f + expf(-v));
        C[(m0 + r) * N + gn] = v;
    }
}

// ================= fused, pipelined FFN =================
// out = relu(A@W1^T+b1) @ W2^T + b2;  A tile resident, W chunks double-buffered.
__global__ void __launch_bounds__(256)
ffn_fused(const float* __restrict__ A, const float* __restrict__ W1,
          const float* __restrict__ B1, const float* __restrict__ W2,
          const float* __restrict__ B2, float* __restrict__ Cout) {
    extern __shared__ float fsm[];
    float* As  = fsm;                      // 128*SE
    float* W1s = As + 128 * SE;            // 2 x 64*SE
    float* W2s = W1s + 2 * 64 * SE;        // 2 x 64*SE
    float* Hs  = W2s + 2 * 64 * SE;        // 128*SE
    const int tid = threadIdx.x;
    const int warp = tid >> 5;
    const int wm = warp >> 1, wn = warp & 1;
    const size_t m0 = (size_t)blockIdx.x * 128;

    float4 wR[4];
    auto loadW1 = [&](int c) {
#pragma unroll
        for (int u = 0; u < 4; u++) {
            int i = tid + u * 256;
            int n = i >> 4, q = i & 15;
            wR[u] = *(const float4*)&W1[((size_t)c * 64 + n) * 64 + q * 4];
        }
    };
    auto stsW1 = [&](int buf) {
        float* d = W1s + buf * 64 * SE;
#pragma unroll
        for (int u = 0; u < 4; u++) {
            int i = tid + u * 256;
            int n = i >> 4, q = i & 15;
            *(float4*)&d[n * SE + q * 4] = to_tf32_4(wR[u]);
        }
    };
    auto loadW2 = [&](int c) {
#pragma unroll
        for (int u = 0; u < 4; u++) {
            int i = tid + u * 256;
            int o = i >> 4, q = i & 15;
            wR[u] = *(const float4*)&W2[(size_t)o * DFFc + c * 64 + q * 4];
        }
    };
    auto stsW2 = [&](int buf) {
        float* d = W2s + buf * 64 * SE;
#pragma unroll
        for (int u = 0; u < 4; u++) {
            int i = tid + u * 256;
            int o = i >> 4, q = i & 15;
            *(float4*)&d[o * SE + q * 4] = to_tf32_4(wR[u]);
        }
    };

    // stage A tile (128 x 64) once
#pragma unroll
    for (int i = tid; i < 128 * 16; i += 256) {
        int row = i >> 4, q = i & 15;
        float4 v = *(const float4*)&A[(m0 + row) * 64 + q * 4];
        *(float4*)&As[row * SE + q * 4] = to_tf32_4(v);
    }
    loadW1(0); stsW1(0);
    loadW2(0); stsW2(0);
    __syncthreads();

    wmma::fragment<wmma::accumulator, 16, 16, 8, float> out[2][2];
#pragma unroll
    for (int i = 0; i < 2; i++)
#pragma unroll
        for (int j = 0; j < 2; j++) wmma::fill_fragment(out[i][j], 0.f);

    for (int c = 0; c < 32; c++) {
        const int buf = c & 1;
        if (c + 1 < 32) loadW1(c + 1);                  // overlaps hid-mma

        float* W1b = W1s + buf * 64 * SE;
        float* W2b = W2s + buf * 64 * SE;

        wmma::fragment<wmma::accumulator, 16, 16, 8, float> hacc[2][2];
#pragma unroll
        for (int i = 0; i < 2; i++)
#pragma unroll
            for (int j = 0; j < 2; j++) wmma::fill_fragment(hacc[i][j], 0.f);
#pragma unroll
        for (int ks = 0; ks < 8; ks++) {
            wmma::fragment<wmma::matrix_a, 16, 16, 8, wmma::precision::tf32, wmma::row_major> a[2];
            wmma::fragment<wmma::matrix_b, 16, 16, 8, wmma::precision::tf32, wmma::col_major> b[2];
#pragma unroll
            for (int i = 0; i < 2; i++)
                wmma::load_matrix_sync(a[i], &As[(wm * 32 + i * 16) * SE + ks * 8], SE);
#pragma unroll
            for (int j = 0; j < 2; j++)
                wmma::load_matrix_sync(b[j], &W1b[(wn * 32 + j * 16) * SE + ks * 8], SE);
#pragma unroll
            for (int i = 0; i < 2; i++)
#pragma unroll
                for (int j = 0; j < 2; j++)
                    wmma::mma_sync(hacc[i][j], a[i], b[j], hacc[i][j]);
        }
#pragma unroll
        for (int i = 0; i < 2; i++)
#pragma unroll
            for (int j = 0; j < 2; j++)
                wmma::store_matrix_sync(&Hs[(wm * 32 + i * 16) * SE + wn * 32 + j * 16],
                                        hacc[i][j], SE, wmma::mem_row_major);
        __syncthreads();

        // bias + relu + tf32 in place; stage next W1 while here
#pragma unroll
        for (int i = tid; i < 128 * 64; i += 256) {
            int r = i >> 6, col = i & 63;
            float v = Hs[r * SE + col] + __ldg(&B1[c * 64 + col]);
            Hs[r * SE + col] = to_tf32(fmaxf(v, 0.f));
        }
        if (c + 1 < 32) stsW1((c + 1) & 1);             // other buffer: safe
        __syncthreads();

        if (c + 1 < 32) loadW2(c + 1);                  // overlaps out-mma
#pragma unroll
        for (int ks = 0; ks < 8; ks++) {
            wmma::fragment<wmma::matrix_a, 16, 16, 8, wmma::precision::tf32, wmma::row_major> a[2];
            wmma::fragment<wmma::matrix_b, 16, 16, 8, wmma::precision::tf32, wmma::col_major> b[2];
#pragma unroll
            for (int i = 0; i < 2; i++)
                wmma::load_matrix_sync(a[i], &Hs[(wm * 32 + i * 16) * SE + ks * 8], SE);
#pragma unroll
            for (int j = 0; j < 2; j++)
                wmma::load_matrix_sync(b[j], &W2b[(wn * 32 + j * 16) * SE + ks * 8], SE);
#pragma unroll
            for (int i = 0; i < 2; i++)
#pragma unroll
                for (int j = 0; j < 2; j++)
                    wmma::mma_sync(out[i][j], a[i], b[j], out[i][j]);
        }
        if (c + 1 < 32) stsW2((c + 1) & 1);
        __syncthreads();
    }

#pragma unroll
    for (int i = 0; i < 2; i++)
#pragma unroll
        for (int j = 0; j < 2; j++)
            wmma::store_matrix_sync(&Hs[(wm * 32 + i * 16) * SE + wn * 32 + j * 16],
                                    out[i][j], SE, wmma::mem_row_major);
    __syncthreads();
#pragma unroll
    for (int i = tid; i < 128 * 64; i += 256) {
        int r = i >> 6, col = i & 63;
        Cout[(m0 + r) * 64 + col] = Hs[r * SE + col] + B2[col];
    }
}

// ---------------- weight reorder: k = ci*9+kk -> kk*Cin+ci ----------------
__global__ void reorder_w(const float* __restrict__ in, float* __restrict__ out,
                          int O, int Cin) {
    int K = Cin * 9;
    int i = blockIdx.x * 256 + threadIdx.x;
    if (i >= O * K) return;
    int o = i / K, k = i % K;
    int kk = k / Cin, ci = k % Cin;
    out[(size_t)o * K + k] = in[(size_t)o * K + ci * 9 + kk];
}

// ---------------- im2col (small layers only) ----------------
__global__ void im2col_k(const float* __restrict__ src, float* __restrict__ dst,
                         int Cin, int nchw) {
    long tid = (long)blockIdx.x * blockDim.x + threadIdx.x;
    long total = (long)MTOK * Cin * 9;
    if (tid >= total) return;
    int kk = (int)(tid % 9);
    long t2 = tid / 9;
    int ci = (int)(t2 % Cin);
    int m  = (int)(t2 / Cin);
    int b = m / HWc, pix = m % HWc;
    int y = pix / Wc, x = pix % Wc;
    int ky = kk / 3, kx = kk % 3;
    int py = y + ky - 1, px = x + kx - 1;
    float v = 0.f;
    if (py >= 0 && py < Hc && px >= 0 && px < Wc) {
        if (nchw) v = src[((size_t)(b * Cin + ci) * HWc) + py * Wc + px];
        else      v = src[((size_t)(b * HWc + py * Wc + px)) * Cin + ci];
    }
    dst[(size_t)m * (Cin * 9) + ci * 9 + kk] = v;
}

// ---------------- attention ----------------
__global__ void attn_k(const float* __restrict__ qkv, float* __restrict__ out) {
    int idx = blockIdx.x * blockDim.x + threadIdx.x;
    if (idx >= HWc * NHc) return;
    int n = idx / NHc, h = idx % NHc;
    const float* r0 = qkv + (size_t)n * 192 + h * DHc;
    const float* r1 = qkv + (size_t)(HWc + n) * 192 + h * DHc;
    const float *q0 = r0, *k0 = r0 + 64, *v0 = r0 + 128;
    const float *q1 = r1, *k1 = r1 + 64, *v1 = r1 + 128;
    float s00 = 0, s01 = 0, s10 = 0, s11 = 0;
#pragma unroll
    for (int d = 0; d < DHc; d++) {
        float a = q0[d], b = q1[d], c = k0[d], e = k1[d];
        s00 += a * c; s01 += a * e; s10 += b * c; s11 += b * e;
    }
    const float sc = 0.25f;
    s00 *= sc; s01 *= sc; s10 *= sc; s11 *= sc;
    float m0 = fmaxf(s00, s01);
    float e00 = expf(s00 - m0), e01 = expf(s01 - m0);
    float p00 = e00 / (e00 + e01), p01 = e01 / (e00 + e01);
    float m1 = fmaxf(s10, s11);
    float e10 = expf(s10 - m1), e11 = expf(s11 - m1);
    float p10 = e10 / (e10 + e11), p11 = e11 / (e10 + e11);
    float* o0 = out + (size_t)n * 64 + h * DHc;
    float* o1 = out + (size_t)(HWc + n) * 64 + h * DHc;
#pragma unroll
    for (int d = 0; d < DHc; d++) {
        o0[d] = p00 * v0[d] + p01 * v1[d];
        o1[d] = p10 * v0[d] + p11 * v1[d];
    }
}

// ---------------- residual + LayerNorm ----------------
__global__ void ln_res_k(const float* __restrict__ a, const float* __restrict__ b,
                         const float* __restrict__ g, const float* __restrict__ be,
                         float* __restrict__ out) {
    int gt = blockIdx.x * blockDim.x + threadIdx.x;
    int warp = gt / 32, lane = gt % 32;
    if (warp >= MTOK) return;
    size_t base = (size_t)warp * 64;
    float x0 = a[base + lane] + b[base + lane];
    float x1 = a[base + 32 + lane] + b[base + 32 + lane];
    float s = x0 + x1;
#pragma unroll
    for (int o = 16; o > 0; o >>= 1) s += __shfl_xor_sync(0xffffffffu, s, o);
    float mu = s * (1.f / 64.f);
    float c0 = x0 - mu, c1 = x1 - mu;
    float sq = c0 * c0 + c1 * c1;
#pragma unroll
    for (int o = 16; o > 0; o >>= 1) sq += __shfl_xor_sync(0xffffffffu, sq, o);
    float r = rsqrtf(sq * (1.f / 64.f) + 1e-5f);
    out[base + lane]      = g[lane] * c0 * r + be[lane];
    out[base + 32 + lane] = g[lane + 32] * c1 * r + be[lane + 32];
}

// ---------------- per-pixel 3x3 adaptive filter ----------------
__global__ void fuse_k(const float* __restrict__ xin, const float* __restrict__ filt,
                       float* __restrict__ out) {
    int m = blockIdx.x * blockDim.x + threadIdx.x;
    if (m >= MTOK) return;
    int b = m / HWc, pix = m % HWc;
    int y = pix / Wc, x = pix % Wc;
    const float* xb = xin + (size_t)b * 3 * HWc;
    float acc = 0.f;
#pragma unroll
    for (int u = 0; u < 3; u++) {
#pragma unroll
        for (int v = 0; v < 3; v++) {
            int py = y + u - 1, px = x + v - 1;
            if (py < 0 || py >= Hc || px < 0 || px >= Wc) continue;
            int p = py * Wc + px;
            float s = xb[p] + xb[HWc + p] + xb[2 * HWc + p];
            acc += filt[(size_t)m * 9 + u * 3 + v] * s;
        }
    }
    out[m] = acc;
}

static void run_gemm(const float* A, const float* W, const float* b, float* C,
                     int N, int K, int act) {
    dim3 g((N + BN - 1) / BN, MTOK / BM);
    wmma_gemm<<<g, 256, GEMM_SMEM>>>(A, W, b, C, N, K, act);
}
static void run_conv(const float* src, int Cin, const float* Wr, const float* b,
                     float* C, int N, int act) {
    dim3 g((N + BN - 1) / BN, MTOK / BM);
    conv_gemm<<<g, 256, GEMM_SMEM>>>(src, Cin, Wr, b, C, N, act);
}

extern "C" void kernel_launch(void* const* d_in, const int* in_sizes, int n_in,
                              void* d_out, int out_size) {
    const float* x        = (const float*)d_in[0];
    const float* enc_w1   = (const float*)d_in[1];
    const float* enc_b1   = (const float*)d_in[2];
    const float* enc_w2   = (const float*)d_in[3];
    const float* enc_b2   = (const float*)d_in[4];
    const float* in_pw    = (const float*)d_in[5];
    const float* in_pb    = (const float*)d_in[6];
    const float* out_pw   = (const float*)d_in[7];
    const float* out_pb   = (const float*)d_in[8];
    const float* ln1_g    = (const float*)d_in[9];
    const float* ln1_b    = (const float*)d_in[10];
    const float* ffn_w1   = (const float*)d_in[11];
    const float* ffn_b1   = (const float*)d_in[12];
    const float* ffn_w2   = (const float*)d_in[13];
    const float* ffn_b2   = (const float*)d_in[14];
    const float* ln2_g    = (const float*)d_in[15];
    const float* ln2_b    = (const float*)d_in[16];
    const float* sf_w1    = (const float*)d_in[17];
    const float* sf_b1    = (const float*)d_in[18];
    const float* sf_w2    = (const float*)d_in[19];
    const float* sf_b2    = (const float*)d_in[20];
    const float* dec_w1   = (const float*)d_in[21];
    const float* dec_b1   = (const float*)d_in[22];
    const float* dec_w2   = (const float*)d_in[23];
    const float* dec_b2   = (const float*)d_in[24];
    float* out = (float*)d_out;

    float *col, *bufA, *t, *qkv, *attn, *t1, *t2, *sf1, *filt, *fus, *d1, *wr;
    cudaGetSymbolAddress((void**)&col,  g_col);
    cudaGetSymbolAddress((void**)&bufA, g_bufA);
    cudaGetSymbolAddress((void**)&t,    g_t);
    cudaGetSymbolAddress((void**)&qkv,  g_qkv);
    cudaGetSymbolAddress((void**)&attn, g_attn);
    cudaGetSymbolAddress((void**)&t1,   g_t1);
    cudaGetSymbolAddress((void**)&t2,   g_t2);
    cudaGetSymbolAddress((void**)&sf1,  g_sf1);
    cudaGetSymbolAddress((void**)&filt, g_filt);
    cudaGetSymbolAddress((void**)&fus,  g_fus);
    cudaGetSymbolAddress((void**)&d1,   g_d1);
    cudaGetSymbolAddress((void**)&wr,   g_wr);

    float* wr_enc2 = wr;
    float* wr_sf1  = wr_enc2 + 64 * 576;
    float* wr_sf2  = wr_sf1 + 32 * 576;
    float* wr_dec2 = wr_sf2 + 9 * 288;

    cudaFuncSetAttribute(wmma_gemm, cudaFuncAttributeMaxDynamicSharedMemorySize, GEMM_SMEM);
    cudaFuncSetAttribute(conv_gemm, cudaFuncAttributeMaxDynamicSharedMemorySize, GEMM_SMEM);
    cudaFuncSetAttribute(ffn_fused, cudaFuncAttributeMaxDynamicSharedMemorySize, FFN_SMEM);

    const int M = MTOK;
    auto blocks = [](long total, int thr) { return (int)((total + thr - 1) / thr); };

    reorder_w<<<blocks(64 * 576, 256), 256>>>(enc_w2, wr_enc2, 64, 64);
    reorder_w<<<blocks(32 * 576, 256), 256>>>(sf_w1, wr_sf1, 32, 64);
    reorder_w<<<blocks(9 * 288, 256), 256>>>(sf_w2, wr_sf2, 9, 32);
    reorder_w<<<blocks(1 * 576, 256), 256>>>(dec_w2, wr_dec2, 1, 64);

    // ---- encoder ----
    im2col_k<<<blocks((long)M * 3 * 9, 256), 256>>>(x, col, 3, 1);
    run_gemm(col, enc_w1, enc_b1, bufA, 64, 27, 1);
    run_conv(bufA, 64, wr_enc2, enc_b2, t, 64, 1);

    // ---- transformer ----
    run_gemm(t, in_pw, in_pb, qkv, 192, 64, 0);
    attn_k<<<blocks((long)HWc * NHc, 256), 256>>>(qkv, attn);
    run_gemm(attn, out_pw, out_pb, bufA, 64, 64, 0);
    ln_res_k<<<blocks((long)M * 32, 256), 256>>>(t, bufA, ln1_g, ln1_b, t1);
    ffn_fused<<<M / 128, 256, FFN_SMEM>>>(t1, ffn_w1, ffn_b1, ffn_w2, ffn_b2, bufA);
    ln_res_k<<<blocks((long)M * 32, 256), 256>>>(t1, bufA, ln2_g, ln2_b, t2);

    // ---- spatial filter branch ----
    run_conv(t2, 64, wr_sf1, sf_b1, sf1, 32, 0);
    run_conv(sf1, 32, wr_sf2, sf_b2, filt, 9, 0);
    fuse_k<<<blocks((long)M, 256), 256>>>(x, filt, fus);

    // ---- decoder ----
    im2col_k<<<blocks((long)M * 1 * 9, 256), 256>>>(fus, col, 1, 0);
    run_gemm(col, dec_w1, dec_b1, d1, 64, 9, 1);
    run_conv(d1, 64, wr_dec2, dec_b2, out, 1, 2);
}

// round 8
// speedup vs baseline: 3.8078x; 1.1066x over previous
#include <cuda_runtime.h>
#include <mma.h>
#include <cstdint>
#include <math.h>

using namespace nvcuda;

#define Hc   224
#define Wc   224
#define HWc  (Hc * Wc)       // 50176
#define Bc   2
#define MTOK (Bc * HWc)      // 100352
#define Ec   64
#define NHc  4
#define DHc  16
#define DFFc 2048

// ---------------- scratch ----------------
__device__ float g_col [MTOK * 27];
__device__ float g_bufA[MTOK * 64];
__device__ float g_t   [MTOK * 64];
__device__ float g_qkv [MTOK * 192];
__device__ float g_attn[MTOK * 64];
__device__ float g_t1  [MTOK * 64];
__device__ float g_t2  [MTOK * 64];
__device__ float g_sf1 [MTOK * 32];
__device__ float g_filt[MTOK * 9];
__device__ float g_fus [MTOK];
__device__ float g_d1  [MTOK * 64];
__device__ float g_wr  [64 * 576 + 32 * 576 + 9 * 288 + 1 * 576];

__device__ __forceinline__ float to_tf32(float x) {
    uint32_t r;
    asm("cvt.rna.tf32.f32 %0, %1;" : "=r"(r) : "f"(x));
    return __uint_as_float(r);
}
__device__ __forceinline__ float4 to_tf32_4(float4 v) {
    return make_float4(to_tf32(v.x), to_tf32(v.y), to_tf32(v.z), to_tf32(v.w));
}

#define SA 36
#define SE 68
#define BM 128
#define BK 32
#define GEMM_SMEM ((2 * BM * SA + 2 * 64 * SA) * 4)
#define FFN_SMEM  ((128 * SE + 2 * 64 * SE + 2 * 64 * SE + 128 * SE) * 4)

// ================= WMMA tf32 GEMM (dense A, BN=64) =================
__global__ void __launch_bounds__(256)
wmma_gemm(const float* __restrict__ A, const float* __restrict__ W,
          const float* __restrict__ bias, float* __restrict__ C,
          int N, int K, int act) {
    extern __shared__ float sm[];
    float* AsB = sm;
    float* BsB = sm + 2 * BM * SA;

    const int tid = threadIdx.x;
    const int warp = tid >> 5;
    const int wm = warp >> 1, wn = warp & 1;
    const size_t m0 = (size_t)blockIdx.y * BM;
    const int n0 = blockIdx.x * 64;
    const bool k4 = ((K & 3) == 0);
    const int chunks = (K + BK - 1) / BK;

    float4 aR[4], bR[2];
    auto load_glb = [&](int k0) {
#pragma unroll
        for (int u = 0; u < 4; u++) {
            int i = tid + u * 256;
            int row = i >> 3, q = i & 7;
            int gk = k0 + q * 4;
            float4 v = make_float4(0.f, 0.f, 0.f, 0.f);
            const float* p = A + (m0 + row) * K + gk;
            if (k4 && gk + 4 <= K) v = *(const float4*)p;
            else if (gk < K) {
                v.x = p[0];
                if (gk + 1 < K) v.y = p[1];
                if (gk + 2 < K) v.z = p[2];
                if (gk + 3 < K) v.w = p[3];
            }
            aR[u] = v;
        }
#pragma unroll
        for (int u = 0; u < 2; u++) {
            int i = tid + u * 256;
            int n = i >> 3, q = i & 7;
            int gn = n0 + n, gk = k0 + q * 4;
            float4 v = make_float4(0.f, 0.f, 0.f, 0.f);
            if (gn < N) {
                const float* p = W + (size_t)gn * K + gk;
                if (k4 && gk + 4 <= K) v = *(const float4*)p;
                else if (gk < K) {
                    v.x = p[0];
                    if (gk + 1 < K) v.y = p[1];
                    if (gk + 2 < K) v.z = p[2];
                    if (gk + 3 < K) v.w = p[3];
                }
            }
            bR[u] = v;
        }
    };
    auto sts_all = [&](int buf) {
        float* Ab = AsB + buf * BM * SA;
        float* Bb = BsB + buf * 64 * SA;
#pragma unroll
        for (int u = 0; u < 4; u++) {
            int i = tid + u * 256;
            int row = i >> 3, q = i & 7;
            *(float4*)&Ab[row * SA + q * 4] = to_tf32_4(aR[u]);
        }
#pragma unroll
        for (int u = 0; u < 2; u++) {
            int i = tid + u * 256;
            int n = i >> 3, q = i & 7;
            *(float4*)&Bb[n * SA + q * 4] = to_tf32_4(bR[u]);
        }
    };

    wmma::fragment<wmma::accumulator, 16, 16, 8, float> acc[2][2];
#pragma unroll
    for (int i = 0; i < 2; i++)
#pragma unroll
        for (int j = 0; j < 2; j++) wmma::fill_fragment(acc[i][j], 0.f);

    load_glb(0); sts_all(0);
    __syncthreads();
    for (int c = 0; c < chunks; c++) {
        const int buf = c & 1;
        if (c + 1 < chunks) load_glb((c + 1) * BK);
        float* Ab = AsB + buf * BM * SA;
        float* Bb = BsB + buf * 64 * SA;
#pragma unroll
        for (int ks = 0; ks < 4; ks++) {
            wmma::fragment<wmma::matrix_a, 16, 16, 8, wmma::precision::tf32, wmma::row_major> a[2];
            wmma::fragment<wmma::matrix_b, 16, 16, 8, wmma::precision::tf32, wmma::col_major> b[2];
#pragma unroll
            for (int i = 0; i < 2; i++)
                wmma::load_matrix_sync(a[i], &Ab[(wm * 32 + i * 16) * SA + ks * 8], SA);
#pragma unroll
            for (int j = 0; j < 2; j++)
                wmma::load_matrix_sync(b[j], &Bb[(wn * 32 + j * 16) * SA + ks * 8], SA);
#pragma unroll
            for (int i = 0; i < 2; i++)
#pragma unroll
                for (int j = 0; j < 2; j++)
                    wmma::mma_sync(acc[i][j], a[i], b[j], acc[i][j]);
        }
        if (c + 1 < chunks) sts_all((c + 1) & 1);
        __syncthreads();
    }

#pragma unroll
    for (int i = 0; i < 2; i++)
#pragma unroll
        for (int j = 0; j < 2; j++)
            wmma::store_matrix_sync(&sm[(wm * 32 + i * 16) * SE + wn * 32 + j * 16],
                                    acc[i][j], SE, wmma::mem_row_major);
    __syncthreads();
    for (int i = tid; i < BM * 64; i += 256) {
        int r = i >> 6, c = i & 63;
        int gn = n0 + c;
        if (gn >= N) continue;
        float v = sm[r * SE + c] + bias[gn];
        if (act == 1) v = fmaxf(v, 0.f);
        else if (act == 2) v = 1.f / (1.f + expf(-v));
        C[(m0 + r) * N + gn] = v;
    }
}

// ======== GEMM (BN=64, K=64) + residual + LayerNorm fused epilogue ========
// outp = LN(res + A@W^T + bias; g, be)
__global__ void __launch_bounds__(256)
wmma_gemm_ln(const float* __restrict__ A, const float* __restrict__ W,
             const float* __restrict__ bias, const float* __restrict__ res,
             const float* __restrict__ g, const float* __restrict__ be,
             float* __restrict__ outp) {
    extern __shared__ float sm[];
    float* AsB = sm;
    float* BsB = sm + 2 * BM * SA;
    const int K = 64;

    const int tid = threadIdx.x;
    const int warp = tid >> 5;
    const int lane = tid & 31;
    const int wm = warp >> 1, wn = warp & 1;
    const size_t m0 = (size_t)blockIdx.y * BM;

    float4 aR[4], bR[2];
    auto load_glb = [&](int k0) {
#pragma unroll
        for (int u = 0; u < 4; u++) {
            int i = tid + u * 256;
            int row = i >> 3, q = i & 7;
            aR[u] = *(const float4*)&A[(m0 + row) * K + k0 + q * 4];
        }
#pragma unroll
        for (int u = 0; u < 2; u++) {
            int i = tid + u * 256;
            int n = i >> 3, q = i & 7;
            bR[u] = *(const float4*)&W[(size_t)n * K + k0 + q * 4];
        }
    };
    auto sts_all = [&](int buf) {
        float* Ab = AsB + buf * BM * SA;
        float* Bb = BsB + buf * 64 * SA;
#pragma unroll
        for (int u = 0; u < 4; u++) {
            int i = tid + u * 256;
            int row = i >> 3, q = i & 7;
            *(float4*)&Ab[row * SA + q * 4] = to_tf32_4(aR[u]);
        }
#pragma unroll
        for (int u = 0; u < 2; u++) {
            int i = tid + u * 256;
            int n = i >> 3, q = i & 7;
            *(float4*)&Bb[n * SA + q * 4] = to_tf32_4(bR[u]);
        }
    };

    wmma::fragment<wmma::accumulator, 16, 16, 8, float> acc[2][2];
#pragma unroll
    for (int i = 0; i < 2; i++)
#pragma unroll
        for (int j = 0; j < 2; j++) wmma::fill_fragment(acc[i][j], 0.f);

    load_glb(0); sts_all(0);
    __syncthreads();
    for (int c = 0; c < 2; c++) {
        const int buf = c & 1;
        if (c == 0) load_glb(BK);
        float* Ab = AsB + buf * BM * SA;
        float* Bb = BsB + buf * 64 * SA;
#pragma unroll
        for (int ks = 0; ks < 4; ks++) {
            wmma::fragment<wmma::matrix_a, 16, 16, 8, wmma::precision::tf32, wmma::row_major> a[2];
            wmma::fragment<wmma::matrix_b, 16, 16, 8, wmma::precision::tf32, wmma::col_major> b[2];
#pragma unroll
            for (int i = 0; i < 2; i++)
                wmma::load_matrix_sync(a[i], &Ab[(wm * 32 + i * 16) * SA + ks * 8], SA);
#pragma unroll
            for (int j = 0; j < 2; j++)
                wmma::load_matrix_sync(b[j], &Bb[(wn * 32 + j * 16) * SA + ks * 8], SA);
#pragma unroll
            for (int i = 0; i < 2; i++)
#pragma unroll
                for (int j = 0; j < 2; j++)
                    wmma::mma_sync(acc[i][j], a[i], b[j], acc[i][j]);
        }
        if (c == 0) sts_all(1);
        __syncthreads();
    }

#pragma unroll
    for (int i = 0; i < 2; i++)
#pragma unroll
        for (int j = 0; j < 2; j++)
            wmma::store_matrix_sync(&sm[(wm * 32 + i * 16) * SE + wn * 32 + j * 16],
                                    acc[i][j], SE, wmma::mem_row_major);
    __syncthreads();
    // fused residual + LN: warp per row group (8 warps x 16 rows)
    for (int r = warp * 16; r < warp * 16 + 16; r++) {
        size_t m = m0 + r;
        float x0 = sm[r * SE + lane] + bias[lane] + res[m * 64 + lane];
        float x1 = sm[r * SE + 32 + lane] + bias[32 + lane] + res[m * 64 + 32 + lane];
        float s = x0 + x1;
#pragma unroll
        for (int o = 16; o > 0; o >>= 1) s += __shfl_xor_sync(0xffffffffu, s, o);
        float mu = s * (1.f / 64.f);
        float c0 = x0 - mu, c1 = x1 - mu;
        float sq = c0 * c0 + c1 * c1;
#pragma unroll
        for (int o = 16; o > 0; o >>= 1) sq += __shfl_xor_sync(0xffffffffu, sq, o);
        float rs = rsqrtf(sq * (1.f / 64.f) + 1e-5f);
        outp[m * 64 + lane]      = g[lane] * c0 * rs + be[lane];
        outp[m * 64 + 32 + lane] = g[lane + 32] * c1 * rs + be[lane + 32];
    }
}

// ================= implicit-im2col conv GEMM, templated BN =================
template<int BNT, int WM, int WN>
__global__ void __launch_bounds__(256)
conv_gemm_t(const float* __restrict__ src, int Cin,
            const float* __restrict__ Wr, const float* __restrict__ bias,
            float* __restrict__ C, int N, int act) {
    constexpr int FM = BM / (WM * 16);
    constexpr int FN = BNT / (WN * 16);
    constexpr int SEB = BNT + 4;
    extern __shared__ float sm[];
    float* AsB = sm;
    float* BsB = sm + 2 * BM * SA;

    const int tid = threadIdx.x;
    const int warp = tid >> 5;
    const int wm = warp / WN, wn = warp % WN;
    const size_t m0 = (size_t)blockIdx.y * BM;
    const int n0 = blockIdx.x * BNT;
    const int K = 9 * Cin;
    const int chunks = K / BK;

    float4 aR[4], bR[(BNT * 8 + 255) / 256];

    auto load_glb = [&](int c) {
        const int k0 = c * BK;
        const int kk = k0 / Cin;
        const int ci0 = k0 % Cin;
        const int ky = kk / 3 - 1, kx = kk % 3 - 1;
#pragma unroll
        for (int u = 0; u < 4; u++) {
            int i = tid + u * 256;
            int row = i >> 3, q = i & 7;
            int m = (int)m0 + row;
            int b = m / HWc, pix = m % HWc;
            int y = pix / Wc, x = pix % Wc;
            int py = y + ky, px = x + kx;
            float4 v = make_float4(0.f, 0.f, 0.f, 0.f);
            if (py >= 0 && py < Hc && px >= 0 && px < Wc)
                v = *(const float4*)&src[((size_t)b * HWc + py * Wc + px) * Cin + ci0 + q * 4];
            aR[u] = v;
        }
#pragma unroll
        for (int u = 0; u < (BNT * 8 + 255) / 256; u++) {
            int i = tid + u * 256;
            float4 v = make_float4(0.f, 0.f, 0.f, 0.f);
            if (i < BNT * 8) {
                int n = i >> 3, q = i & 7;
                int gn = n0 + n;
                if (gn < N) v = *(const float4*)&Wr[(size_t)gn * K + k0 + q * 4];
            }
            bR[u] = v;
        }
    };
    auto sts_all = [&](int buf) {
        float* Ab = AsB + buf * BM * SA;
        float* Bb = BsB + buf * BNT * SA;
#pragma unroll
        for (int u = 0; u < 4; u++) {
            int i = tid + u * 256;
            int row = i >> 3, q = i & 7;
            *(float4*)&Ab[row * SA + q * 4] = to_tf32_4(aR[u]);
        }
#pragma unroll
        for (int u = 0; u < (BNT * 8 + 255) / 256; u++) {
            int i = tid + u * 256;
            if (i < BNT * 8) {
                int n = i >> 3, q = i & 7;
                *(float4*)&Bb[n * SA + q * 4] = to_tf32_4(bR[u]);
            }
        }
    };

    wmma::fragment<wmma::accumulator, 16, 16, 8, float> acc[FM][FN];
#pragma unroll
    for (int i = 0; i < FM; i++)
#pragma unroll
        for (int j = 0; j < FN; j++) wmma::fill_fragment(acc[i][j], 0.f);

    load_glb(0); sts_all(0);
    __syncthreads();
    for (int c = 0; c < chunks; c++) {
        const int buf = c & 1;
        if (c + 1 < chunks) load_glb(c + 1);
        float* Ab = AsB + buf * BM * SA;
        float* Bb = BsB + buf * BNT * SA;
#pragma unroll
        for (int ks = 0; ks < 4; ks++) {
            wmma::fragment<wmma::matrix_a, 16, 16, 8, wmma::precision::tf32, wmma::row_major> a[FM];
            wmma::fragment<wmma::matrix_b, 16, 16, 8, wmma::precision::tf32, wmma::col_major> b[FN];
#pragma unroll
            for (int i = 0; i < FM; i++)
                wmma::load_matrix_sync(a[i], &Ab[((wm * FM + i) * 16) * SA + ks * 8], SA);
#pragma unroll
            for (int j = 0; j < FN; j++)
                wmma::load_matrix_sync(b[j], &Bb[((wn * FN + j) * 16) * SA + ks * 8], SA);
#pragma unroll
            for (int i = 0; i < FM; i++)
#pragma unroll
                for (int j = 0; j < FN; j++)
                    wmma::mma_sync(acc[i][j], a[i], b[j], acc[i][j]);
        }
        if (c + 1 < chunks) sts_all((c + 1) & 1);
        __syncthreads();
    }

#pragma unroll
    for (int i = 0; i < FM; i++)
#pragma unroll
        for (int j = 0; j < FN; j++)
            wmma::store_matrix_sync(&sm[((wm * FM + i) * 16) * SEB + (wn * FN + j) * 16],
                                    acc[i][j], SEB, wmma::mem_row_major);
    __syncthreads();
    for (int i = tid; i < BM * BNT; i += 256) {
        int r = i / BNT, col = i % BNT;
        int gn = n0 + col;
        if (gn >= N) continue;
        float v = sm[r * SEB + col] + bias[gn];
        if (act == 1) v = fmaxf(v, 0.f);
        else if (act == 2) v = 1.f / (1.f + expf(-v));
        C[(m0 + r) * N + gn] = v;
    }
}

// ================= fused FFN + residual + LN2 =================
__global__ void __launch_bounds__(256)
ffn_fused(const float* __restrict__ A, const float* __restrict__ W1,
          const float* __restrict__ B1, const float* __restrict__ W2,
          const float* __restrict__ B2,
          const float* __restrict__ g2, const float* __restrict__ be2,
          float* __restrict__ T2out) {
    extern __shared__ float fsm[];
    float* As  = fsm;
    float* W1s = As + 128 * SE;
    float* W2s = W1s + 2 * 64 * SE;
    float* Hs  = W2s + 2 * 64 * SE;
    const int tid = threadIdx.x;
    const int warp = tid >> 5;
    const int lane = tid & 31;
    const int wm = warp >> 1, wn = warp & 1;
    const size_t m0 = (size_t)blockIdx.x * 128;

    float4 wR[4];
    auto loadW1 = [&](int c) {
#pragma unroll
        for (int u = 0; u < 4; u++) {
            int i = tid + u * 256;
            int n = i >> 4, q = i & 15;
            wR[u] = *(const float4*)&W1[((size_t)c * 64 + n) * 64 + q * 4];
        }
    };
    auto stsW1 = [&](int buf) {
        float* d = W1s + buf * 64 * SE;
#pragma unroll
        for (int u = 0; u < 4; u++) {
            int i = tid + u * 256;
            int n = i >> 4, q = i & 15;
            *(float4*)&d[n * SE + q * 4] = to_tf32_4(wR[u]);
        }
    };
    auto loadW2 = [&](int c) {
#pragma unroll
        for (int u = 0; u < 4; u++) {
            int i = tid + u * 256;
            int o = i >> 4, q = i & 15;
            wR[u] = *(const float4*)&W2[(size_t)o * DFFc + c * 64 + q * 4];
        }
    };
    auto stsW2 = [&](int buf) {
        float* d = W2s + buf * 64 * SE;
#pragma unroll
        for (int u = 0; u < 4; u++) {
            int i = tid + u * 256;
            int o = i >> 4, q = i & 15;
            *(float4*)&d[o * SE + q * 4] = to_tf32_4(wR[u]);
        }
    };

#pragma unroll
    for (int i = tid; i < 128 * 16; i += 256) {
        int row = i >> 4, q = i & 15;
        float4 v = *(const float4*)&A[(m0 + row) * 64 + q * 4];
        *(float4*)&As[row * SE + q * 4] = to_tf32_4(v);
    }
    loadW1(0); stsW1(0);
    loadW2(0); stsW2(0);
    __syncthreads();

    wmma::fragment<wmma::accumulator, 16, 16, 8, float> out[2][2];
#pragma unroll
    for (int i = 0; i < 2; i++)
#pragma unroll
        for (int j = 0; j < 2; j++) wmma::fill_fragment(out[i][j], 0.f);

    for (int c = 0; c < 32; c++) {
        const int buf = c & 1;
        if (c + 1 < 32) loadW1(c + 1);
        float* W1b = W1s + buf * 64 * SE;
        float* W2b = W2s + buf * 64 * SE;

        wmma::fragment<wmma::accumulator, 16, 16, 8, float> hacc[2][2];
#pragma unroll
        for (int i = 0; i < 2; i++)
#pragma unroll
            for (int j = 0; j < 2; j++) wmma::fill_fragment(hacc[i][j], 0.f);
#pragma unroll
        for (int ks = 0; ks < 8; ks++) {
            wmma::fragment<wmma::matrix_a, 16, 16, 8, wmma::precision::tf32, wmma::row_major> a[2];
            wmma::fragment<wmma::matrix_b, 16, 16, 8, wmma::precision::tf32, wmma::col_major> b[2];
#pragma unroll
            for (int i = 0; i < 2; i++)
                wmma::load_matrix_sync(a[i], &As[(wm * 32 + i * 16) * SE + ks * 8], SE);
#pragma unroll
            for (int j = 0; j < 2; j++)
                wmma::load_matrix_sync(b[j], &W1b[(wn * 32 + j * 16) * SE + ks * 8], SE);
#pragma unroll
            for (int i = 0; i < 2; i++)
#pragma unroll
                for (int j = 0; j < 2; j++)
                    wmma::mma_sync(hacc[i][j], a[i], b[j], hacc[i][j]);
        }
#pragma unroll
        for (int i = 0; i < 2; i++)
#pragma unroll
            for (int j = 0; j < 2; j++)
                wmma::store_matrix_sync(&Hs[(wm * 32 + i * 16) * SE + wn * 32 + j * 16],
                                        hacc[i][j], SE, wmma::mem_row_major);
        __syncthreads();
#pragma unroll
        for (int i = tid; i < 128 * 64; i += 256) {
            int r = i >> 6, col = i & 63;
            float v = Hs[r * SE + col] + __ldg(&B1[c * 64 + col]);
            Hs[r * SE + col] = to_tf32(fmaxf(v, 0.f));
        }
        if (c + 1 < 32) stsW1((c + 1) & 1);
        __syncthreads();

        if (c + 1 < 32) loadW2(c + 1);
#pragma unroll
        for (int ks = 0; ks < 8; ks++) {
            wmma::fragment<wmma::matrix_a, 16, 16, 8, wmma::precision::tf32, wmma::row_major> a[2];
            wmma::fragment<wmma::matrix_b, 16, 16, 8, wmma::precision::tf32, wmma::col_major> b[2];
#pragma unroll
            for (int i = 0; i < 2; i++)
                wmma::load_matrix_sync(a[i], &Hs[(wm * 32 + i * 16) * SE + ks * 8], SE);
#pragma unroll
            for (int j = 0; j < 2; j++)
                wmma::load_matrix_sync(b[j], &W2b[(wn * 32 + j * 16) * SE + ks * 8], SE);
#pragma unroll
            for (int i = 0; i < 2; i++)
#pragma unroll
                for (int j = 0; j < 2; j++)
                    wmma::mma_sync(out[i][j], a[i], b[j], out[i][j]);
        }
        if (c + 1 < 32) stsW2((c + 1) & 1);
        __syncthreads();
    }

#pragma unroll
    for (int i = 0; i < 2; i++)
#pragma unroll
        for (int j = 0; j < 2; j++)
            wmma::store_matrix_sync(&Hs[(wm * 32 + i * 16) * SE + wn * 32 + j * 16],
                                    out[i][j], SE, wmma::mem_row_major);
    __syncthreads();
    // fused residual + LN2 (residual read fresh from A in fp32)
    for (int r = warp * 16; r < warp * 16 + 16; r++) {
        size_t m = m0 + r;
        float x0 = Hs[r * SE + lane] + B2[lane] + A[m * 64 + lane];
        float x1 = Hs[r * SE + 32 + lane] + B2[32 + lane] + A[m * 64 + 32 + lane];
        float s = x0 + x1;
#pragma unroll
        for (int o = 16; o > 0; o >>= 1) s += __shfl_xor_sync(0xffffffffu, s, o);
        float mu = s * (1.f / 64.f);
        float c0 = x0 - mu, c1 = x1 - mu;
        float sq = c0 * c0 + c1 * c1;
#pragma unroll
        for (int o = 16; o > 0; o >>= 1) sq += __shfl_xor_sync(0xffffffffu, sq, o);
        float rs = rsqrtf(sq * (1.f / 64.f) + 1e-5f);
        T2out[m * 64 + lane]      = g2[lane] * c0 * rs + be2[lane];
        T2out[m * 64 + 32 + lane] = g2[lane + 32] * c1 * rs + be2[lane + 32];
    }
}

// ---------------- weight reorder ----------------
__global__ void reorder_w(const float* __restrict__ in, float* __restrict__ out,
                          int O, int Cin) {
    int K = Cin * 9;
    int i = blockIdx.x * 256 + threadIdx.x;
    if (i >= O * K) return;
    int o = i / K, k = i % K;
    int kk = k / Cin, ci = k % Cin;
    out[(size_t)o * K + k] = in[(size_t)o * K + ci * 9 + kk];
}

// ---------------- im2col (small layers only) ----------------
__global__ void im2col_k(const float* __restrict__ src, float* __restrict__ dst,
                         int Cin, int nchw) {
    long tid = (long)blockIdx.x * blockDim.x + threadIdx.x;
    long total = (long)MTOK * Cin * 9;
    if (tid >= total) return;
    int kk = (int)(tid % 9);
    long t2 = tid / 9;
    int ci = (int)(t2 % Cin);
    int m  = (int)(t2 / Cin);
    int b = m / HWc, pix = m % HWc;
    int y = pix / Wc, x = pix % Wc;
    int ky = kk / 3, kx = kk % 3;
    int py = y + ky - 1, px = x + kx - 1;
    float v = 0.f;
    if (py >= 0 && py < Hc && px >= 0 && px < Wc) {
        if (nchw) v = src[((size_t)(b * Cin + ci) * HWc) + py * Wc + px];
        else      v = src[((size_t)(b * HWc + py * Wc + px)) * Cin + ci];
    }
    dst[(size_t)m * (Cin * 9) + ci * 9 + kk] = v;
}

// ---------------- attention ----------------
__global__ void attn_k(const float* __restrict__ qkv, float* __restrict__ out) {
    int idx = blockIdx.x * blockDim.x + threadIdx.x;
    if (idx >= HWc * NHc) return;
    int n = idx / NHc, h = idx % NHc;
    const float* r0 = qkv + (size_t)n * 192 + h * DHc;
    const float* r1 = qkv + (size_t)(HWc + n) * 192 + h * DHc;
    const float *q0 = r0, *k0 = r0 + 64, *v0 = r0 + 128;
    const float *q1 = r1, *k1 = r1 + 64, *v1 = r1 + 128;
    float s00 = 0, s01 = 0, s10 = 0, s11 = 0;
#pragma unroll
    for (int d = 0; d < DHc; d++) {
        float a = q0[d], b = q1[d], c = k0[d], e = k1[d];
        s00 += a * c; s01 += a * e; s10 += b * c; s11 += b * e;
    }
    const float sc = 0.25f;
    s00 *= sc; s01 *= sc; s10 *= sc; s11 *= sc;
    float m0 = fmaxf(s00, s01);
    float e00 = expf(s00 - m0), e01 = expf(s01 - m0);
    float p00 = e00 / (e00 + e01), p01 = e01 / (e00 + e01);
    float m1 = fmaxf(s10, s11);
    float e10 = expf(s10 - m1), e11 = expf(s11 - m1);
    float p10 = e10 / (e10 + e11), p11 = e11 / (e10 + e11);
    float* o0 = out + (size_t)n * 64 + h * DHc;
    float* o1 = out + (size_t)(HWc + n) * 64 + h * DHc;
#pragma unroll
    for (int d = 0; d < DHc; d++) {
        o0[d] = p00 * v0[d] + p01 * v1[d];
        o1[d] = p10 * v0[d] + p11 * v1[d];
    }
}

// ---------------- per-pixel 3x3 adaptive filter ----------------
__global__ void fuse_k(const float* __restrict__ xin, const float* __restrict__ filt,
                       float* __restrict__ out) {
    int m = blockIdx.x * blockDim.x + threadIdx.x;
    if (m >= MTOK) return;
    int b = m / HWc, pix = m % HWc;
    int y = pix / Wc, x = pix % Wc;
    const float* xb = xin + (size_t)b * 3 * HWc;
    float acc = 0.f;
#pragma unroll
    for (int u = 0; u < 3; u++) {
#pragma unroll
        for (int v = 0; v < 3; v++) {
            int py = y + u - 1, px = x + v - 1;
            if (py < 0 || py >= Hc || px < 0 || px >= Wc) continue;
            int p = py * Wc + px;
            float s = xb[p] + xb[HWc + p] + xb[2 * HWc + p];
            acc += filt[(size_t)m * 9 + u * 3 + v] * s;
        }
    }
    out[m] = acc;
}

static void run_gemm(const float* A, const float* W, const float* b, float* C,
                     int N, int K, int act) {
    dim3 g((N + 63) / 64, MTOK / BM);
    wmma_gemm<<<g, 256, GEMM_SMEM>>>(A, W, b, C, N, K, act);
}
template<int BNT, int WM, int WN>
static void run_conv_t(const float* src, int Cin, const float* Wr, const float* b,
                       float* C, int N, int act) {
    constexpr int SM1 = (2 * BM * SA + 2 * BNT * SA) * 4;
    constexpr int SM2 = (BM * (BNT + 4)) * 4;
    constexpr int SM = SM1 > SM2 ? SM1 : SM2;
    cudaFuncSetAttribute(conv_gemm_t<BNT, WM, WN>,
                         cudaFuncAttributeMaxDynamicSharedMemorySize, SM);
    dim3 g((N + BNT - 1) / BNT, MTOK / BM);
    conv_gemm_t<BNT, WM, WN><<<g, 256, SM>>>(src, Cin, Wr, b, C, N, act);
}

extern "C" void kernel_launch(void* const* d_in, const int* in_sizes, int n_in,
                              void* d_out, int out_size) {
    const float* x        = (const float*)d_in[0];
    const float* enc_w1   = (const float*)d_in[1];
    const float* enc_b1   = (const float*)d_in[2];
    const float* enc_w2   = (const float*)d_in[3];
    const float* enc_b2   = (const float*)d_in[4];
    const float* in_pw    = (const float*)d_in[5];
    const float* in_pb    = (const float*)d_in[6];
    const float* out_pw   = (const float*)d_in[7];
    const float* out_pb   = (const float*)d_in[8];
    const float* ln1_g    = (const float*)d_in[9];
    const float* ln1_b    = (const float*)d_in[10];
    const float* ffn_w1   = (const float*)d_in[11];
    const float* ffn_b1   = (const float*)d_in[12];
    const float* ffn_w2   = (const float*)d_in[13];
    const float* ffn_b2   = (const float*)d_in[14];
    const float* ln2_g    = (const float*)d_in[15];
    const float* ln2_b    = (const float*)d_in[16];
    const float* sf_w1    = (const float*)d_in[17];
    const float* sf_b1    = (const float*)d_in[18];
    const float* sf_w2    = (const float*)d_in[19];
    const float* sf_b2    = (const float*)d_in[20];
    const float* dec_w1   = (const float*)d_in[21];
    const float* dec_b1   = (const float*)d_in[22];
    const float* dec_w2   = (const float*)d_in[23];
    const float* dec_b2   = (const float*)d_in[24];
    float* out = (float*)d_out;

    float *col, *bufA, *t, *qkv, *attn, *t1, *t2, *sf1, *filt, *fus, *d1, *wr;
    cudaGetSymbolAddress((void**)&col,  g_col);
    cudaGetSymbolAddress((void**)&bufA, g_bufA);
    cudaGetSymbolAddress((void**)&t,    g_t);
    cudaGetSymbolAddress((void**)&qkv,  g_qkv);
    cudaGetSymbolAddress((void**)&attn, g_attn);
    cudaGetSymbolAddress((void**)&t1,   g_t1);
    cudaGetSymbolAddress((void**)&t2,   g_t2);
    cudaGetSymbolAddress((void**)&sf1,  g_sf1);
    cudaGetSymbolAddress((void**)&filt, g_filt);
    cudaGetSymbolAddress((void**)&fus,  g_fus);
    cudaGetSymbolAddress((void**)&d1,   g_d1);
    cudaGetSymbolAddress((void**)&wr,   g_wr);

    float* wr_enc2 = wr;
    float* wr_sf1  = wr_enc2 + 64 * 576;
    float* wr_sf2  = wr_sf1 + 32 * 576;
    float* wr_dec2 = wr_sf2 + 9 * 288;

    cudaFuncSetAttribute(wmma_gemm, cudaFuncAttributeMaxDynamicSharedMemorySize, GEMM_SMEM);
    cudaFuncSetAttribute(wmma_gemm_ln, cudaFuncAttributeMaxDynamicSharedMemorySize, GEMM_SMEM);
    cudaFuncSetAttribute(ffn_fused, cudaFuncAttributeMaxDynamicSharedMemorySize, FFN_SMEM);

    const int M = MTOK;
    auto blocks = [](long total, int thr) { return (int)((total + thr - 1) / thr); };

    reorder_w<<<blocks(64 * 576, 256), 256>>>(enc_w2, wr_enc2, 64, 64);
    reorder_w<<<blocks(32 * 576, 256), 256>>>(sf_w1, wr_sf1, 32, 64);
    reorder_w<<<blocks(9 * 288, 256), 256>>>(sf_w2, wr_sf2, 9, 32);
    reorder_w<<<blocks(1 * 576, 256), 256>>>(dec_w2, wr_dec2, 1, 64);

    // ---- encoder ----
    im2col_k<<<blocks((long)M * 3 * 9, 256), 256>>>(x, col, 3, 1);
    run_gemm(col, enc_w1, enc_b1, bufA, 64, 27, 1);
    run_conv_t<64, 4, 2>(bufA, 64, wr_enc2, enc_b2, t, 64, 1);

    // ---- transformer ----
    run_gemm(t, in_pw, in_pb, qkv, 192, 64, 0);
    attn_k<<<blocks((long)HWc * NHc, 256), 256>>>(qkv, attn);
    {   // out_proj + residual(t) + LN1 -> t1
        dim3 g(1, MTOK / BM);
        wmma_gemm_ln<<<g, 256, GEMM_SMEM>>>(attn, out_pw, out_pb, t, ln1_g, ln1_b, t1);
    }
    ffn_fused<<<M / 128, 256, FFN_SMEM>>>(t1, ffn_w1, ffn_b1, ffn_w2, ffn_b2,
                                          ln2_g, ln2_b, t2);

    // ---- spatial filter branch ----
    run_conv_t<32, 4, 2>(t2, 64, wr_sf1, sf_b1, sf1, 32, 0);
    run_conv_t<16, 8, 1>(sf1, 32, wr_sf2, sf_b2, filt, 9, 0);
    fuse_k<<<blocks((long)M, 256), 256>>>(x, filt, fus);

    // ---- decoder ----
    im2col_k<<<blocks((long)M * 1 * 9, 256), 256>>>(fus, col, 1, 0);
    run_gemm(col, dec_w1, dec_b1, d1, 64, 9, 1);
    run_conv_t<16, 8, 1>(d1, 64, wr_dec2, dec_b2, out, 1, 2);
}

// round 9
// speedup vs baseline: 4.1244x; 1.0831x over previous
#include <cuda_runtime.h>
#include <mma.h>
#include <cstdint>
#include <math.h>

using namespace nvcuda;

#define Hc   224
#define Wc   224
#define HWc  (Hc * Wc)
#define Bc   2
#define MTOK (Bc * HWc)      // 100352
#define Ec   64
#define NHc  4
#define DHc  16
#define DFFc 2048

// ---------------- scratch ----------------
__device__ float g_col [MTOK * 27];
__device__ float g_bufA[MTOK * 64];
__device__ float g_t   [MTOK * 64];
__device__ float g_qkv [MTOK * 192];
__device__ float g_attn[MTOK * 64];
__device__ float g_t1  [MTOK * 64];
__device__ float g_t2  [MTOK * 64];
__device__ float g_sf1 [MTOK * 32];
__device__ float g_filt[MTOK * 9];
__device__ float g_fus [MTOK];
__device__ float g_d1  [MTOK * 64];
__device__ float g_wr  [64 * 576 + 32 * 576 + 9 * 288 + 1 * 576];

__device__ __forceinline__ float to_tf32(float x) {
    uint32_t r;
    asm("cvt.rna.tf32.f32 %0, %1;" : "=r"(r) : "f"(x));
    return __uint_as_float(r);
}
__device__ __forceinline__ float4 to_tf32_4(float4 v) {
    return make_float4(to_tf32(v.x), to_tf32(v.y), to_tf32(v.z), to_tf32(v.w));
}

#define SA 36
#define SE 68
#define FSA 76      // FFN stage-1 tiles: 72 used cols (64 + bias col + pad)
#define BK 32
#define GEMM_SMEM ((2 * 128 * SA + 2 * 64 * SA) * 4)
#define FFN_SMEM ((128 * FSA + 2 * 64 * FSA + 2 * 64 * SE + 128 * SE) * 4)

// ================= WMMA tf32 GEMM (dense A, BM=128, BN=64) =================
__global__ void __launch_bounds__(256)
wmma_gemm(const float* __restrict__ A, const float* __restrict__ W,
          const float* __restrict__ bias, float* __restrict__ C,
          int N, int K, int act) {
    extern __shared__ float sm[];
    float* AsB = sm;
    float* BsB = sm + 2 * 128 * SA;

    const int tid = threadIdx.x;
    const int warp = tid >> 5;
    const int wm = warp >> 1, wn = warp & 1;
    const size_t m0 = (size_t)blockIdx.y * 128;
    const int n0 = blockIdx.x * 64;
    const bool k4 = ((K & 3) == 0);
    const int chunks = (K + BK - 1) / BK;

    float4 aR[4], bR[2];
    auto load_glb = [&](int k0) {
#pragma unroll
        for (int u = 0; u < 4; u++) {
            int i = tid + u * 256;
            int row = i >> 3, q = i & 7;
            int gk = k0 + q * 4;
            float4 v = make_float4(0.f, 0.f, 0.f, 0.f);
            const float* p = A + (m0 + row) * K + gk;
            if (k4 && gk + 4 <= K) v = *(const float4*)p;
            else if (gk < K) {
                v.x = p[0];
                if (gk + 1 < K) v.y = p[1];
                if (gk + 2 < K) v.z = p[2];
                if (gk + 3 < K) v.w = p[3];
            }
            aR[u] = v;
        }
#pragma unroll
        for (int u = 0; u < 2; u++) {
            int i = tid + u * 256;
            int n = i >> 3, q = i & 7;
            int gn = n0 + n, gk = k0 + q * 4;
            float4 v = make_float4(0.f, 0.f, 0.f, 0.f);
            if (gn < N) {
                const float* p = W + (size_t)gn * K + gk;
                if (k4 && gk + 4 <= K) v = *(const float4*)p;
                else if (gk < K) {
                    v.x = p[0];
                    if (gk + 1 < K) v.y = p[1];
                    if (gk + 2 < K) v.z = p[2];
                    if (gk + 3 < K) v.w = p[3];
                }
            }
            bR[u] = v;
        }
    };
    auto sts_all = [&](int buf) {
        float* Ab = AsB + buf * 128 * SA;
        float* Bb = BsB + buf * 64 * SA;
#pragma unroll
        for (int u = 0; u < 4; u++) {
            int i = tid + u * 256;
            int row = i >> 3, q = i & 7;
            *(float4*)&Ab[row * SA + q * 4] = to_tf32_4(aR[u]);
        }
#pragma unroll
        for (int u = 0; u < 2; u++) {
            int i = tid + u * 256;
            int n = i >> 3, q = i & 7;
            *(float4*)&Bb[n * SA + q * 4] = to_tf32_4(bR[u]);
        }
    };

    wmma::fragment<wmma::accumulator, 16, 16, 8, float> acc[2][2];
#pragma unroll
    for (int i = 0; i < 2; i++)
#pragma unroll
        for (int j = 0; j < 2; j++) wmma::fill_fragment(acc[i][j], 0.f);

    load_glb(0); sts_all(0);
    __syncthreads();
    for (int c = 0; c < chunks; c++) {
        const int buf = c & 1;
        if (c + 1 < chunks) load_glb((c + 1) * BK);
        float* Ab = AsB + buf * 128 * SA;
        float* Bb = BsB + buf * 64 * SA;
#pragma unroll
        for (int ks = 0; ks < 4; ks++) {
            wmma::fragment<wmma::matrix_a, 16, 16, 8, wmma::precision::tf32, wmma::row_major> a[2];
            wmma::fragment<wmma::matrix_b, 16, 16, 8, wmma::precision::tf32, wmma::col_major> b[2];
#pragma unroll
            for (int i = 0; i < 2; i++)
                wmma::load_matrix_sync(a[i], &Ab[(wm * 32 + i * 16) * SA + ks * 8], SA);
#pragma unroll
            for (int j = 0; j < 2; j++)
                wmma::load_matrix_sync(b[j], &Bb[(wn * 32 + j * 16) * SA + ks * 8], SA);
#pragma unroll
            for (int i = 0; i < 2; i++)
#pragma unroll
                for (int j = 0; j < 2; j++)
                    wmma::mma_sync(acc[i][j], a[i], b[j], acc[i][j]);
        }
        if (c + 1 < chunks) sts_all((c + 1) & 1);
        __syncthreads();
    }

#pragma unroll
    for (int i = 0; i < 2; i++)
#pragma unroll
        for (int j = 0; j < 2; j++)
            wmma::store_matrix_sync(&sm[(wm * 32 + i * 16) * SE + wn * 32 + j * 16],
                                    acc[i][j], SE, wmma::mem_row_major);
    __syncthreads();
    for (int i = tid; i < 128 * 64; i += 256) {
        int r = i >> 6, c = i & 63;
        int gn = n0 + c;
        if (gn >= N) continue;
        float v = sm[r * SE + c] + bias[gn];
        if (act == 1) v = fmaxf(v, 0.f);
        else if (act == 2) v = 1.f / (1.f + expf(-v));
        C[(m0 + r) * N + gn] = v;
    }
}

// ======== GEMM (BN=64, K=64) + residual + LayerNorm fused epilogue ========
__global__ void __launch_bounds__(256)
wmma_gemm_ln(const float* __restrict__ A, const float* __restrict__ W,
             const float* __restrict__ bias, const float* __restrict__ res,
             const float* __restrict__ g, const float* __restrict__ be,
             float* __restrict__ outp) {
    extern __shared__ float sm[];
    float* AsB = sm;
    float* BsB = sm + 2 * 128 * SA;
    const int K = 64;

    const int tid = threadIdx.x;
    const int warp = tid >> 5;
    const int lane = tid & 31;
    const int wm = warp >> 1, wn = warp & 1;
    const size_t m0 = (size_t)blockIdx.y * 128;

    float4 aR[4], bR[2];
    auto load_glb = [&](int k0) {
#pragma unroll
        for (int u = 0; u < 4; u++) {
            int i = tid + u * 256;
            int row = i >> 3, q = i & 7;
            aR[u] = *(const float4*)&A[(m0 + row) * K + k0 + q * 4];
        }
#pragma unroll
        for (int u = 0; u < 2; u++) {
            int i = tid + u * 256;
            int n = i >> 3, q = i & 7;
            bR[u] = *(const float4*)&W[(size_t)n * K + k0 + q * 4];
        }
    };
    auto sts_all = [&](int buf) {
        float* Ab = AsB + buf * 128 * SA;
        float* Bb = BsB + buf * 64 * SA;
#pragma unroll
        for (int u = 0; u < 4; u++) {
            int i = tid + u * 256;
            int row = i >> 3, q = i & 7;
            *(float4*)&Ab[row * SA + q * 4] = to_tf32_4(aR[u]);
        }
#pragma unroll
        for (int u = 0; u < 2; u++) {
            int i = tid + u * 256;
            int n = i >> 3, q = i & 7;
            *(float4*)&Bb[n * SA + q * 4] = to_tf32_4(bR[u]);
        }
    };

    wmma::fragment<wmma::accumulator, 16, 16, 8, float> acc[2][2];
#pragma unroll
    for (int i = 0; i < 2; i++)
#pragma unroll
        for (int j = 0; j < 2; j++) wmma::fill_fragment(acc[i][j], 0.f);

    load_glb(0); sts_all(0);
    __syncthreads();
    for (int c = 0; c < 2; c++) {
        const int buf = c & 1;
        if (c == 0) load_glb(BK);
        float* Ab = AsB + buf * 128 * SA;
        float* Bb = BsB + buf * 64 * SA;
#pragma unroll
        for (int ks = 0; ks < 4; ks++) {
            wmma::fragment<wmma::matrix_a, 16, 16, 8, wmma::precision::tf32, wmma::row_major> a[2];
            wmma::fragment<wmma::matrix_b, 16, 16, 8, wmma::precision::tf32, wmma::col_major> b[2];
#pragma unroll
            for (int i = 0; i < 2; i++)
                wmma::load_matrix_sync(a[i], &Ab[(wm * 32 + i * 16) * SA + ks * 8], SA);
#pragma unroll
            for (int j = 0; j < 2; j++)
                wmma::load_matrix_sync(b[j], &Bb[(wn * 32 + j * 16) * SA + ks * 8], SA);
#pragma unroll
            for (int i = 0; i < 2; i++)
#pragma unroll
                for (int j = 0; j < 2; j++)
                    wmma::mma_sync(acc[i][j], a[i], b[j], acc[i][j]);
        }
        if (c == 0) sts_all(1);
        __syncthreads();
    }

#pragma unroll
    for (int i = 0; i < 2; i++)
#pragma unroll
        for (int j = 0; j < 2; j++)
            wmma::store_matrix_sync(&sm[(wm * 32 + i * 16) * SE + wn * 32 + j * 16],
                                    acc[i][j], SE, wmma::mem_row_major);
    __syncthreads();
    for (int r = warp * 16; r < warp * 16 + 16; r++) {
        size_t m = m0 + r;
        float x0 = sm[r * SE + lane] + bias[lane] + res[m * 64 + lane];
        float x1 = sm[r * SE + 32 + lane] + bias[32 + lane] + res[m * 64 + 32 + lane];
        float s = x0 + x1;
#pragma unroll
        for (int o = 16; o > 0; o >>= 1) s += __shfl_xor_sync(0xffffffffu, s, o);
        float mu = s * (1.f / 64.f);
        float c0 = x0 - mu, c1 = x1 - mu;
        float sq = c0 * c0 + c1 * c1;
#pragma unroll
        for (int o = 16; o > 0; o >>= 1) sq += __shfl_xor_sync(0xffffffffu, sq, o);
        float rs = rsqrtf(sq * (1.f / 64.f) + 1e-5f);
        outp[m * 64 + lane]      = g[lane] * c0 * rs + be[lane];
        outp[m * 64 + 32 + lane] = g[lane + 32] * c1 * rs + be[lane + 32];
    }
}

// ================= implicit-im2col conv GEMM, templated BM/BN =================
template<int BMT, int BNT, int WM, int WN>
__global__ void __launch_bounds__(256)
conv_gemm_t(const float* __restrict__ src, int Cin,
            const float* __restrict__ Wr, const float* __restrict__ bias,
            float* __restrict__ C, int N, int act) {
    constexpr int FM = BMT / (WM * 16);
    constexpr int FN = BNT / (WN * 16);
    constexpr int SEB = BNT + 4;
    constexpr int AU = BMT / 32;                 // float4s per thread for A
    constexpr int BU = (BNT * 8 + 255) / 256;
    extern __shared__ float sm[];
    float* AsB = sm;
    float* BsB = sm + 2 * BMT * SA;

    const int tid = threadIdx.x;
    const int warp = tid >> 5;
    const int wm = warp / WN, wn = warp % WN;
    const size_t m0 = (size_t)blockIdx.y * BMT;
    const int n0 = blockIdx.x * BNT;
    const int K = 9 * Cin;
    const int chunks = K / BK;

    float4 aR[AU], bR[BU];

    auto load_glb = [&](int c) {
        const int k0 = c * BK;
        const int kk = k0 / Cin;
        const int ci0 = k0 % Cin;
        const int ky = kk / 3 - 1, kx = kk % 3 - 1;
#pragma unroll
        for (int u = 0; u < AU; u++) {
            int i = tid + u * 256;
            int row = i >> 3, q = i & 7;
            int m = (int)m0 + row;
            int b = m / HWc, pix = m % HWc;
            int y = pix / Wc, x = pix % Wc;
            int py = y + ky, px = x + kx;
            float4 v = make_float4(0.f, 0.f, 0.f, 0.f);
            if (py >= 0 && py < Hc && px >= 0 && px < Wc)
                v = *(const float4*)&src[((size_t)b * HWc + py * Wc + px) * Cin + ci0 + q * 4];
            aR[u] = v;
        }
#pragma unroll
        for (int u = 0; u < BU; u++) {
            int i = tid + u * 256;
            float4 v = make_float4(0.f, 0.f, 0.f, 0.f);
            if (i < BNT * 8) {
                int n = i >> 3, q = i & 7;
                int gn = n0 + n;
                if (gn < N) v = *(const float4*)&Wr[(size_t)gn * K + k0 + q * 4];
            }
            bR[u] = v;
        }
    };
    auto sts_all = [&](int buf) {
        float* Ab = AsB + buf * BMT * SA;
        float* Bb = BsB + buf * BNT * SA;
#pragma unroll
        for (int u = 0; u < AU; u++) {
            int i = tid + u * 256;
            int row = i >> 3, q = i & 7;
            *(float4*)&Ab[row * SA + q * 4] = to_tf32_4(aR[u]);
        }
#pragma unroll
        for (int u = 0; u < BU; u++) {
            int i = tid + u * 256;
            if (i < BNT * 8) {
                int n = i >> 3, q = i & 7;
                *(float4*)&Bb[n * SA + q * 4] = to_tf32_4(bR[u]);
            }
        }
    };

    wmma::fragment<wmma::accumulator, 16, 16, 8, float> acc[FM][FN];
#pragma unroll
    for (int i = 0; i < FM; i++)
#pragma unroll
        for (int j = 0; j < FN; j++) wmma::fill_fragment(acc[i][j], 0.f);

    load_glb(0); sts_all(0);
    __syncthreads();
    for (int c = 0; c < chunks; c++) {
        const int buf = c & 1;
        if (c + 1 < chunks) load_glb(c + 1);
        float* Ab = AsB + buf * BMT * SA;
        float* Bb = BsB + buf * BNT * SA;
#pragma unroll
        for (int ks = 0; ks < 4; ks++) {
            wmma::fragment<wmma::matrix_a, 16, 16, 8, wmma::precision::tf32, wmma::row_major> a[FM];
            wmma::fragment<wmma::matrix_b, 16, 16, 8, wmma::precision::tf32, wmma::col_major> b[FN];
#pragma unroll
            for (int i = 0; i < FM; i++)
                wmma::load_matrix_sync(a[i], &Ab[((wm * FM + i) * 16) * SA + ks * 8], SA);
#pragma unroll
            for (int j = 0; j < FN; j++)
                wmma::load_matrix_sync(b[j], &Bb[((wn * FN + j) * 16) * SA + ks * 8], SA);
#pragma unroll
            for (int i = 0; i < FM; i++)
#pragma unroll
                for (int j = 0; j < FN; j++)
                    wmma::mma_sync(acc[i][j], a[i], b[j], acc[i][j]);
        }
        if (c + 1 < chunks) sts_all((c + 1) & 1);
        __syncthreads();
    }

#pragma unroll
    for (int i = 0; i < FM; i++)
#pragma unroll
        for (int j = 0; j < FN; j++)
            wmma::store_matrix_sync(&sm[((wm * FM + i) * 16) * SEB + (wn * FN + j) * 16],
                                    acc[i][j], SEB, wmma::mem_row_major);
    __syncthreads();
    for (int i = tid; i < BMT * BNT; i += 256) {
        int r = i / BNT, col = i % BNT;
        int gn = n0 + col;
        if (gn >= N) continue;
        float v = sm[r * SEB + col] + bias[gn];
        if (act == 1) v = fmaxf(v, 0.f);
        else if (act == 2) v = 1.f / (1.f + expf(-v));
        C[(m0 + r) * N + gn] = v;
    }
}

// ================= fused FFN + residual + LN2 =================
// bias folded via rank-1 K-extension; relu+tf32 applied on accumulator regs.
__global__ void __launch_bounds__(256)
ffn_fused(const float* __restrict__ A, const float* __restrict__ W1,
          const float* __restrict__ B1, const float* __restrict__ W2,
          const float* __restrict__ B2,
          const float* __restrict__ g2, const float* __restrict__ be2,
          float* __restrict__ T2out) {
    extern __shared__ float fsm[];
    float* As  = fsm;                          // 128 x FSA (cols 0..63 data, 64 = 1.0)
    float* W1s = As + 128 * FSA;               // 2 x 64 x FSA (col 64 = bias)
    float* W2s = W1s + 2 * 64 * FSA;           // 2 x 64 x SE
    float* Hs  = W2s + 2 * 64 * SE;            // 128 x SE
    const int tid = threadIdx.x;
    const int warp = tid >> 5;
    const int lane = tid & 31;
    const int wm = warp >> 1, wn = warp & 1;
    const size_t m0 = (size_t)blockIdx.x * 128;

    float4 wR[4];
    auto loadW1 = [&](int c) {
#pragma unroll
        for (int u = 0; u < 4; u++) {
            int i = tid + u * 256;
            int n = i >> 4, q = i & 15;
            wR[u] = *(const float4*)&W1[((size_t)c * 64 + n) * 64 + q * 4];
        }
    };
    auto stsW1 = [&](int buf, int c) {
        float* d = W1s + buf * 64 * FSA;
#pragma unroll
        for (int u = 0; u < 4; u++) {
            int i = tid + u * 256;
            int n = i >> 4, q = i & 15;
            *(float4*)&d[n * FSA + q * 4] = to_tf32_4(wR[u]);
        }
        if (tid < 64) {   // bias column + zero pad (cols 64..75)
            float bv = to_tf32(__ldg(&B1[(size_t)c * 64 + tid]));
            *(float4*)&d[tid * FSA + 64] = make_float4(bv, 0.f, 0.f, 0.f);
            *(float4*)&d[tid * FSA + 68] = make_float4(0.f, 0.f, 0.f, 0.f);
            *(float4*)&d[tid * FSA + 72] = make_float4(0.f, 0.f, 0.f, 0.f);
        }
    };
    auto loadW2 = [&](int c) {
#pragma unroll
        for (int u = 0; u < 4; u++) {
            int i = tid + u * 256;
            int o = i >> 4, q = i & 15;
            wR[u] = *(const float4*)&W2[(size_t)o * DFFc + c * 64 + q * 4];
        }
    };
    auto stsW2 = [&](int buf) {
        float* d = W2s + buf * 64 * SE;
#pragma unroll
        for (int u = 0; u < 4; u++) {
            int i = tid + u * 256;
            int o = i >> 4, q = i & 15;
            *(float4*)&d[o * SE + q * 4] = to_tf32_4(wR[u]);
        }
    };

    // stage A tile once; col 64 = 1.0 (bias lane), 65..75 = 0
#pragma unroll
    for (int i = tid; i < 128 * 16; i += 256) {
        int row = i >> 4, q = i & 15;
        float4 v = *(const float4*)&A[(m0 + row) * 64 + q * 4];
        *(float4*)&As[row * FSA + q * 4] = to_tf32_4(v);
    }
    for (int row = tid; row < 128; row += 256) {
        *(float4*)&As[row * FSA + 64] = make_float4(1.f, 0.f, 0.f, 0.f);
        *(float4*)&As[row * FSA + 68] = make_float4(0.f, 0.f, 0.f, 0.f);
        *(float4*)&As[row * FSA + 72] = make_float4(0.f, 0.f, 0.f, 0.f);
    }
    loadW1(0); stsW1(0, 0);
    loadW2(0); stsW2(0);
    __syncthreads();

    wmma::fragment<wmma::accumulator, 16, 16, 8, float> out[2][2];
#pragma unroll
    for (int i = 0; i < 2; i++)
#pragma unroll
        for (int j = 0; j < 2; j++) wmma::fill_fragment(out[i][j], 0.f);

    for (int c = 0; c < 32; c++) {
        const int buf = c & 1;
        if (c + 1 < 32) loadW1(c + 1);
        float* W1b = W1s + buf * 64 * FSA;
        float* W2b = W2s + buf * 64 * SE;

        // stage1: hid = [A | 1] @ [W1c | b1]^T   (K = 72, 9 ks steps)
        wmma::fragment<wmma::accumulator, 16, 16, 8, float> hacc[2][2];
#pragma unroll
        for (int i = 0; i < 2; i++)
#pragma unroll
            for (int j = 0; j < 2; j++) wmma::fill_fragment(hacc[i][j], 0.f);
#pragma unroll
        for (int ks = 0; ks < 9; ks++) {
            wmma::fragment<wmma::matrix_a, 16, 16, 8, wmma::precision::tf32, wmma::row_major> a[2];
            wmma::fragment<wmma::matrix_b, 16, 16, 8, wmma::precision::tf32, wmma::col_major> b[2];
#pragma unroll
            for (int i = 0; i < 2; i++)
                wmma::load_matrix_sync(a[i], &As[(wm * 32 + i * 16) * FSA + ks * 8], FSA);
#pragma unroll
            for (int j = 0; j < 2; j++)
                wmma::load_matrix_sync(b[j], &W1b[(wn * 32 + j * 16) * FSA + ks * 8], FSA);
#pragma unroll
            for (int i = 0; i < 2; i++)
#pragma unroll
                for (int j = 0; j < 2; j++)
                    wmma::mma_sync(hacc[i][j], a[i], b[j], hacc[i][j]);
        }
        // relu + tf32 on registers, then park in Hs
#pragma unroll
        for (int i = 0; i < 2; i++)
#pragma unroll
            for (int j = 0; j < 2; j++) {
#pragma unroll
                for (int e = 0; e < hacc[i][j].num_elements; e++)
                    hacc[i][j].x[e] = to_tf32(fmaxf(hacc[i][j].x[e], 0.f));
                wmma::store_matrix_sync(&Hs[(wm * 32 + i * 16) * SE + wn * 32 + j * 16],
                                        hacc[i][j], SE, wmma::mem_row_major);
            }
        if (c + 1 < 32) stsW1((c + 1) & 1, c + 1);
        __syncthreads();

        if (c + 1 < 32) loadW2(c + 1);
#pragma unroll
        for (int ks = 0; ks < 8; ks++) {
            wmma::fragment<wmma::matrix_a, 16, 16, 8, wmma::precision::tf32, wmma::row_major> a[2];
            wmma::fragment<wmma::matrix_b, 16, 16, 8, wmma::precision::tf32, wmma::col_major> b[2];
#pragma unroll
            for (int i = 0; i < 2; i++)
                wmma::load_matrix_sync(a[i], &Hs[(wm * 32 + i * 16) * SE + ks * 8], SE);
#pragma unroll
            for (int j = 0; j < 2; j++)
                wmma::load_matrix_sync(b[j], &W2b[(wn * 32 + j * 16) * SE + ks * 8], SE);
#pragma unroll
            for (int i = 0; i < 2; i++)
#pragma unroll
                for (int j = 0; j < 2; j++)
                    wmma::mma_sync(out[i][j], a[i], b[j], out[i][j]);
        }
        if (c + 1 < 32) stsW2((c + 1) & 1);
        __syncthreads();
    }

#pragma unroll
    for (int i = 0; i < 2; i++)
#pragma unroll
        for (int j = 0; j < 2; j++)
            wmma::store_matrix_sync(&Hs[(wm * 32 + i * 16) * SE + wn * 32 + j * 16],
                                    out[i][j], SE, wmma::mem_row_major);
    __syncthreads();
    for (int r = warp * 16; r < warp * 16 + 16; r++) {
        size_t m = m0 + r;
        float x0 = Hs[r * SE + lane] + B2[lane] + A[m * 64 + lane];
        float x1 = Hs[r * SE + 32 + lane] + B2[32 + lane] + A[m * 64 + 32 + lane];
        float s = x0 + x1;
#pragma unroll
        for (int o = 16; o > 0; o >>= 1) s += __shfl_xor_sync(0xffffffffu, s, o);
        float mu = s * (1.f / 64.f);
        float c0 = x0 - mu, c1 = x1 - mu;
        float sq = c0 * c0 + c1 * c1;
#pragma unroll
        for (int o = 16; o > 0; o >>= 1) sq += __shfl_xor_sync(0xffffffffu, sq, o);
        float rs = rsqrtf(sq * (1.f / 64.f) + 1e-5f);
        T2out[m * 64 + lane]      = g2[lane] * c0 * rs + be2[lane];
        T2out[m * 64 + 32 + lane] = g2[lane + 32] * c1 * rs + be2[lane + 32];
    }
}

// ---------------- weight reorder ----------------
__global__ void reorder_w(const float* __restrict__ in, float* __restrict__ out,
                          int O, int Cin) {
    int K = Cin * 9;
    int i = blockIdx.x * 256 + threadIdx.x;
    if (i >= O * K) return;
    int o = i / K, k = i % K;
    int kk = k / Cin, ci = k % Cin;
    out[(size_t)o * K + k] = in[(size_t)o * K + ci * 9 + kk];
}

// ---------------- im2col ----------------
__global__ void im2col_k(const float* __restrict__ src, float* __restrict__ dst,
                         int Cin, int nchw) {
    long tid = (long)blockIdx.x * blockDim.x + threadIdx.x;
    long total = (long)MTOK * Cin * 9;
    if (tid >= total) return;
    int kk = (int)(tid % 9);
    long t2 = tid / 9;
    int ci = (int)(t2 % Cin);
    int m  = (int)(t2 / Cin);
    int b = m / HWc, pix = m % HWc;
    int y = pix / Wc, x = pix % Wc;
    int ky = kk / 3, kx = kk % 3;
    int py = y + ky - 1, px = x + kx - 1;
    float v = 0.f;
    if (py >= 0 && py < Hc && px >= 0 && px < Wc) {
        if (nchw) v = src[((size_t)(b * Cin + ci) * HWc) + py * Wc + px];
        else      v = src[((size_t)(b * HWc + py * Wc + px)) * Cin + ci];
    }
    dst[(size_t)m * (Cin * 9) + ci * 9 + kk] = v;
}

// ---------------- attention ----------------
__global__ void attn_k(const float* __restrict__ qkv, float* __restrict__ out) {
    int idx = blockIdx.x * blockDim.x + threadIdx.x;
    if (idx >= HWc * NHc) return;
    int n = idx / NHc, h = idx % NHc;
    const float* r0 = qkv + (size_t)n * 192 + h * DHc;
    const float* r1 = qkv + (size_t)(HWc + n) * 192 + h * DHc;
    const float *q0 = r0, *k0 = r0 + 64, *v0 = r0 + 128;
    const float *q1 = r1, *k1 = r1 + 64, *v1 = r1 + 128;
    float s00 = 0, s01 = 0, s10 = 0, s11 = 0;
#pragma unroll
    for (int d = 0; d < DHc; d++) {
        float a = q0[d], b = q1[d], c = k0[d], e = k1[d];
        s00 += a * c; s01 += a * e; s10 += b * c; s11 += b * e;
    }
    const float sc = 0.25f;
    s00 *= sc; s01 *= sc; s10 *= sc; s11 *= sc;
    float m0 = fmaxf(s00, s01);
    float e00 = expf(s00 - m0), e01 = expf(s01 - m0);
    float p00 = e00 / (e00 + e01), p01 = e01 / (e00 + e01);
    float m1 = fmaxf(s10, s11);
    float e10 = expf(s10 - m1), e11 = expf(s11 - m1);
    float p10 = e10 / (e10 + e11), p11 = e11 / (e10 + e11);
    float* o0 = out + (size_t)n * 64 + h * DHc;
    float* o1 = out + (size_t)(HWc + n) * 64 + h * DHc;
#pragma unroll
    for (int d = 0; d < DHc; d++) {
        o0[d] = p00 * v0[d] + p01 * v1[d];
        o1[d] = p10 * v0[d] + p11 * v1[d];
    }
}

// ---------------- per-pixel 3x3 adaptive filter ----------------
__global__ void fuse_k(const float* __restrict__ xin, const float* __restrict__ filt,
                       float* __restrict__ out) {
    int m = blockIdx.x * blockDim.x + threadIdx.x;
    if (m >= MTOK) return;
    int b = m / HWc, pix = m % HWc;
    int y = pix / Wc, x = pix % Wc;
    const float* xb = xin + (size_t)b * 3 * HWc;
    float acc = 0.f;
#pragma unroll
    for (int u = 0; u < 3; u++) {
#pragma unroll
        for (int v = 0; v < 3; v++) {
            int py = y + u - 1, px = x + v - 1;
            if (py < 0 || py >= Hc || px < 0 || px >= Wc) continue;
            int p = py * Wc + px;
            float s = xb[p] + xb[HWc + p] + xb[2 * HWc + p];
            acc += filt[(size_t)m * 9 + u * 3 + v] * s;
        }
    }
    out[m] = acc;
}

static void run_gemm(const float* A, const float* W, const float* b, float* C,
                     int N, int K, int act) {
    dim3 g((N + 63) / 64, MTOK / 128);
    wmma_gemm<<<g, 256, GEMM_SMEM>>>(A, W, b, C, N, K, act);
}
template<int BMT, int BNT, int WM, int WN>
static void run_conv_t(const float* src, int Cin, const float* Wr, const float* b,
                       float* C, int N, int act) {
    constexpr int SM1 = (2 * BMT * SA + 2 * BNT * SA) * 4;
    constexpr int SM2 = (BMT * (BNT + 4)) * 4;
    constexpr int SM = SM1 > SM2 ? SM1 : SM2;
    cudaFuncSetAttribute(conv_gemm_t<BMT, BNT, WM, WN>,
                         cudaFuncAttributeMaxDynamicSharedMemorySize, SM);
    dim3 g((N + BNT - 1) / BNT, MTOK / BMT);
    conv_gemm_t<BMT, BNT, WM, WN><<<g, 256, SM>>>(src, Cin, Wr, b, C, N, act);
}

extern "C" void kernel_launch(void* const* d_in, const int* in_sizes, int n_in,
                              void* d_out, int out_size) {
    const float* x        = (const float*)d_in[0];
    const float* enc_w1   = (const float*)d_in[1];
    const float* enc_b1   = (const float*)d_in[2];
    const float* enc_w2   = (const float*)d_in[3];
    const float* enc_b2   = (const float*)d_in[4];
    const float* in_pw    = (const float*)d_in[5];
    const float* in_pb    = (const float*)d_in[6];
    const float* out_pw   = (const float*)d_in[7];
    const float* out_pb   = (const float*)d_in[8];
    const float* ln1_g    = (const float*)d_in[9];
    const float* ln1_b    = (const float*)d_in[10];
    const float* ffn_w1   = (const float*)d_in[11];
    const float* ffn_b1   = (const float*)d_in[12];
    const float* ffn_w2   = (const float*)d_in[13];
    const float* ffn_b2   = (const float*)d_in[14];
    const float* ln2_g    = (const float*)d_in[15];
    const float* ln2_b    = (const float*)d_in[16];
    const float* sf_w1    = (const float*)d_in[17];
    const float* sf_b1    = (const float*)d_in[18];
    const float* sf_w2    = (const float*)d_in[19];
    const float* sf_b2    = (const float*)d_in[20];
    const float* dec_w1   = (const float*)d_in[21];
    const float* dec_b1   = (const float*)d_in[22];
    const float* dec_w2   = (const float*)d_in[23];
    const float* dec_b2   = (const float*)d_in[24];
    float* out = (float*)d_out;

    float *col, *bufA, *t, *qkv, *attn, *t1, *t2, *sf1, *filt, *fus, *d1, *wr;
    cudaGetSymbolAddress((void**)&col,  g_col);
    cudaGetSymbolAddress((void**)&bufA, g_bufA);
    cudaGetSymbolAddress((void**)&t,    g_t);
    cudaGetSymbolAddress((void**)&qkv,  g_qkv);
    cudaGetSymbolAddress((void**)&attn, g_attn);
    cudaGetSymbolAddress((void**)&t1,   g_t1);
    cudaGetSymbolAddress((void**)&t2,   g_t2);
    cudaGetSymbolAddress((void**)&sf1,  g_sf1);
    cudaGetSymbolAddress((void**)&filt, g_filt);
    cudaGetSymbolAddress((void**)&fus,  g_fus);
    cudaGetSymbolAddress((void**)&d1,   g_d1);
    cudaGetSymbolAddress((void**)&wr,   g_wr);

    float* wr_enc2 = wr;
    float* wr_sf1  = wr_enc2 + 64 * 576;
    float* wr_sf2  = wr_sf1 + 32 * 576;
    float* wr_dec2 = wr_sf2 + 9 * 288;

    cudaFuncSetAttribute(wmma_gemm, cudaFuncAttributeMaxDynamicSharedMemorySize, GEMM_SMEM);
    cudaFuncSetAttribute(wmma_gemm_ln, cudaFuncAttributeMaxDynamicSharedMemorySize, GEMM_SMEM);
    cudaFuncSetAttribute(ffn_fused, cudaFuncAttributeMaxDynamicSharedMemorySize, FFN_SMEM);

    const int M = MTOK;
    auto blocks = [](long total, int thr) { return (int)((total + thr - 1) / thr); };

    reorder_w<<<blocks(64 * 576, 256), 256>>>(enc_w2, wr_enc2, 64, 64);
    reorder_w<<<blocks(32 * 576, 256), 256>>>(sf_w1, wr_sf1, 32, 64);
    reorder_w<<<blocks(9 * 288, 256), 256>>>(sf_w2, wr_sf2, 9, 32);
    reorder_w<<<blocks(1 * 576, 256), 256>>>(dec_w2, wr_dec2, 1, 64);

    // ---- encoder ----
    im2col_k<<<blocks((long)M * 3 * 9, 256), 256>>>(x, col, 3, 1);
    run_gemm(col, enc_w1, enc_b1, bufA, 64, 27, 1);
    run_conv_t<256, 64, 4, 2>(bufA, 64, wr_enc2, enc_b2, t, 64, 1);

    // ---- transformer ----
    run_gemm(t, in_pw, in_pb, qkv, 192, 64, 0);
    attn_k<<<blocks((long)HWc * NHc, 256), 256>>>(qkv, attn);
    {
        dim3 g(1, MTOK / 128);
        wmma_gemm_ln<<<g, 256, GEMM_SMEM>>>(attn, out_pw, out_pb, t, ln1_g, ln1_b, t1);
    }
    ffn_fused<<<M / 128, 256, FFN_SMEM>>>(t1, ffn_w1, ffn_b1, ffn_w2, ffn_b2,
                                          ln2_g, ln2_b, t2);

    // ---- spatial filter branch ----
    run_conv_t<256, 32, 4, 2>(t2, 64, wr_sf1, sf_b1, sf1, 32, 0);
    run_conv_t<128, 16, 8, 1>(sf1, 32, wr_sf2, sf_b2, filt, 9, 0);
    fuse_k<<<blocks((long)M, 256), 256>>>(x, filt, fus);

    // ---- decoder ----
    im2col_k<<<blocks((long)M * 1 * 9, 256), 256>>>(fus, col, 1, 0);
    run_gemm(col, dec_w1, dec_b1, d1, 64, 9, 1);
    run_conv_t<256, 16, 8, 1>(d1, 64, wr_dec2, dec_b2, out, 1, 2);
}